// round 10
// baseline (speedup 1.0000x reference)
#include <cuda_runtime.h>
#include <cuda_bf16.h>
#include <cstdint>

#define ST 144                  // row stride bytes (72 bf16): bank-rotating, 16B-aligned
// per-graph tile regions: GB(gi) = gi*27648
#define ADJ_R 0                 // adjacency -> h3 hi
#define XH_R  9216              // X^T hi / T hi / h3 lo
#define XL_R  18432             // X^T lo / T lo   (head: Wf1^T half1 hi(g0)/lo(g1))
#define WH_O  55296             // shared W^T hi (scratch pre-loop; head: Wf1^T half0 hi)
#define WL_O  64512             // shared W^T lo (head: Wf1^T half0 lo)
#define DINV_O 73728            // +gi*256
#define BW_O   74240            // 512B: bias (layers) / wf2 (head)
#define U_O    74752            // +gi*512
#define MP_O   75776            // +gi*512: mean|h3s -> part overlay
#define SMEM_BYTES 76800
#define HB1H_O 18432            // head half1 hi = XL of graph 0
#define HB1L_O 46080            // head half1 lo = XL of graph 1

static __device__ __align__(16) unsigned char g_WT[3][2][9216];   // W_L^T [n][k] hi/lo
static __device__ __align__(16) unsigned char g_Wf1T[2][18432];   // Wf1_dev^T [m][k] hi/lo

__device__ __forceinline__ uint32_t smem_u32(const void* p) {
    uint32_t a;
    asm("{ .reg .u64 t; cvta.to.shared.u64 t, %1; cvt.u32.u64 %0, t; }" : "=r"(a) : "l"(p));
    return a;
}
__device__ __forceinline__ void cpasync16(uint32_t dst, const void* src) {
    asm volatile("cp.async.cg.shared.global [%0], [%1], 16;" :: "r"(dst), "l"(src));
}
#define CP_COMMIT() asm volatile("cp.async.commit_group;" ::: "memory")
#define CP_WAIT0()  asm volatile("cp.async.wait_group 0;" ::: "memory")
#define BARG(id)    asm volatile("bar.sync %0, 128;" :: "r"(id) : "memory")

__device__ __forceinline__ void ldsm4(uint32_t addr, uint32_t* r) {
    asm volatile("ldmatrix.sync.aligned.m8n8.x4.shared.b16 {%0,%1,%2,%3}, [%4];"
                 : "=r"(r[0]), "=r"(r[1]), "=r"(r[2]), "=r"(r[3]) : "r"(addr));
}
__device__ __forceinline__ void mma16816(float* d, const uint32_t* a, const uint32_t* b) {
    asm volatile("mma.sync.aligned.m16n8k16.row.col.f32.bf16.bf16.f32 "
        "{%0,%1,%2,%3}, {%4,%5,%6,%7}, {%8,%9}, {%0,%1,%2,%3};"
        : "+f"(d[0]), "+f"(d[1]), "+f"(d[2]), "+f"(d[3])
        : "r"(a[0]), "r"(a[1]), "r"(a[2]), "r"(a[3]), "r"(b[0]), "r"(b[1]));
}
__device__ __forceinline__ void sp1(float v, uint16_t& h, uint16_t& l) {
    __nv_bfloat16 hb = __float2bfloat16(v);
    __nv_bfloat16 lb = __float2bfloat16(v - __bfloat162float(hb));
    h = __bfloat16_as_ushort(hb); l = __bfloat16_as_ushort(lb);
}
__device__ __forceinline__ uint32_t sp2(float a, float b, uint32_t& lo) {
    uint16_t ah, al, bh, bl; sp1(a, ah, al); sp1(b, bh, bl);
    lo = (uint32_t)al | ((uint32_t)bl << 16);
    return (uint32_t)ah | ((uint32_t)bh << 16);
}
__device__ __forceinline__ float rdbf(const unsigned char* sm, int off, int r, int c) {
    return __bfloat162float(*(const __nv_bfloat16*)(sm + off + r * ST + c * 2));
}

// D(32x32) += A @ B^T over K=64; acc[mt*4+nt][4]: rows m0+mt*16+g(+8), cols n0+nt*8+c0b(+1)
__device__ __forceinline__ void gprod32(uint32_t aB, uint32_t bB, int lane, float (*acc)[4]) {
    const int arow = lane & 15, acol = (lane >> 4) << 3;
    const int brow = (lane & 7) + ((lane & 16) >> 1), bcol = lane & 8;
    #pragma unroll
    for (int kk = 0; kk < 64; kk += 16) {
        uint32_t a0[4], a1[4];
        ldsm4(aB + arow * ST + (kk + acol) * 2, a0);
        ldsm4(aB + (16 + arow) * ST + (kk + acol) * 2, a1);
        #pragma unroll
        for (int nt = 0; nt < 2; nt++) {
            uint32_t bf[4]; ldsm4(bB + (nt * 16 + brow) * ST + (kk + bcol) * 2, bf);
            mma16816(acc[nt * 2],     a0, bf);
            mma16816(acc[nt * 2 + 1], a0, bf + 2);
            mma16816(acc[4 + nt * 2],     a1, bf);
            mma16816(acc[4 + nt * 2 + 1], a1, bf + 2);
        }
    }
}
// acc += A@B1^T + A@B2^T (A fragments loaded once)
__device__ __forceinline__ void gprod32_dualB(uint32_t aB, uint32_t b1B, uint32_t b2B,
                                              int lane, float (*acc)[4]) {
    const int arow = lane & 15, acol = (lane >> 4) << 3;
    const int brow = (lane & 7) + ((lane & 16) >> 1), bcol = lane & 8;
    #pragma unroll
    for (int kk = 0; kk < 64; kk += 16) {
        uint32_t a0[4], a1[4];
        ldsm4(aB + arow * ST + (kk + acol) * 2, a0);
        ldsm4(aB + (16 + arow) * ST + (kk + acol) * 2, a1);
        #pragma unroll
        for (int nt = 0; nt < 2; nt++) {
            uint32_t bf[4];
            ldsm4(b1B + (nt * 16 + brow) * ST + (kk + bcol) * 2, bf);
            mma16816(acc[nt * 2], a0, bf);     mma16816(acc[nt * 2 + 1], a0, bf + 2);
            mma16816(acc[4 + nt * 2], a1, bf); mma16816(acc[4 + nt * 2 + 1], a1, bf + 2);
            ldsm4(b2B + (nt * 16 + brow) * ST + (kk + bcol) * 2, bf);
            mma16816(acc[nt * 2], a0, bf);     mma16816(acc[nt * 2 + 1], a0, bf + 2);
            mma16816(acc[4 + nt * 2], a1, bf); mma16816(acc[4 + nt * 2 + 1], a1, bf + 2);
        }
    }
}
// acc += A1@B^T + A2@B^T (B fragments loaded once)
__device__ __forceinline__ void gprod32_dualA(uint32_t a1B, uint32_t a2B, uint32_t bB,
                                              int lane, float (*acc)[4]) {
    const int arow = lane & 15, acol = (lane >> 4) << 3;
    const int brow = (lane & 7) + ((lane & 16) >> 1), bcol = lane & 8;
    #pragma unroll
    for (int kk = 0; kk < 64; kk += 16) {
        uint32_t a0[4], a1[4], a2[4], a3[4];
        ldsm4(a1B + arow * ST + (kk + acol) * 2, a0);
        ldsm4(a1B + (16 + arow) * ST + (kk + acol) * 2, a1);
        ldsm4(a2B + arow * ST + (kk + acol) * 2, a2);
        ldsm4(a2B + (16 + arow) * ST + (kk + acol) * 2, a3);
        #pragma unroll
        for (int nt = 0; nt < 2; nt++) {
            uint32_t bf[4]; ldsm4(bB + (nt * 16 + brow) * ST + (kk + bcol) * 2, bf);
            mma16816(acc[nt * 2],     a0, bf); mma16816(acc[nt * 2 + 1], a0, bf + 2);
            mma16816(acc[4 + nt * 2], a1, bf); mma16816(acc[4 + nt * 2 + 1], a1, bf + 2);
            mma16816(acc[nt * 2],     a2, bf); mma16816(acc[nt * 2 + 1], a2, bf + 2);
            mma16816(acc[4 + nt * 2], a3, bf); mma16816(acc[4 + nt * 2 + 1], a3, bf + 2);
        }
    }
}

__global__ void pgcn_prep(const float* __restrict__ W1, const float* __restrict__ W2,
                          const float* __restrict__ W3, const float* __restrict__ Wf1) {
    const float* Ws[3] = {W1, W2, W3};
    int gt = blockIdx.x * blockDim.x + threadIdx.x, nth = gridDim.x * blockDim.x;
    for (int L = 0; L < 3; L++)
        for (int i = gt; i < 4096; i += nth) {
            int n = i >> 6, k = i & 63;
            uint16_t h, l; sp1(Ws[L][k * 64 + n], h, l);
            *(uint16_t*)(g_WT[L][0] + n * ST + k * 2) = h;
            *(uint16_t*)(g_WT[L][1] + n * ST + k * 2) = l;
        }
    for (int i = gt; i < 8192; i += nth) {
        int m = i >> 6, k = i & 63;
        uint16_t h, l; sp1(Wf1[k * 128 + m], h, l);
        *(uint16_t*)(g_Wf1T[0] + m * ST + k * 2) = h;
        *(uint16_t*)(g_Wf1T[1] + m * ST + k * 2) = l;
    }
}

__global__ __launch_bounds__(256, 3)
void pgcn_main(const float* __restrict__ dev_obs, const float* __restrict__ srv_obs,
               const float* __restrict__ adj,
               const float* __restrict__ W_dev, const float* __restrict__ b_dev,
               const float* __restrict__ W_srv, const float* __restrict__ b_srv,
               const float* __restrict__ b1, const float* __restrict__ b2,
               const float* __restrict__ b3,
               const float* __restrict__ Wf1, const float* __restrict__ bf1,
               const float* __restrict__ Wf2, const float* __restrict__ bf2,
               float* __restrict__ out)
{
    extern __shared__ __align__(16) unsigned char sm[];
    const uint32_t sb = smem_u32(sm);
    const int tid = threadIdx.x, lane = tid & 31, wid = tid >> 5;
    const int b0 = blockIdx.x * 2;
    const int gi = wid >> 2, w4 = wid & 3;
    const int m0 = (w4 & 1) * 32, n0 = (w4 >> 1) * 32;
    const int g = lane >> 2, c0b = (lane & 3) * 2;
    const uint32_t GB = (uint32_t)gi * 27648u;
    const int barid = gi + 1;
    float* s_dinv = (float*)(sm + DINV_O + gi * 256);
    float* s_bw   = (float*)(sm + BW_O);
    float* s_u    = (float*)(sm + U_O + gi * 512);

    // ---- scratch: ew in WH; obs per graph in WL; masks in WH tail ----
    float* s_ew = (float*)(sm + WH_O);
    for (int i = tid; i < 896; i += 256) s_ew[i] = W_dev[i];
    if (tid < 192) s_ew[896 + tid] = W_srv[tid];
    for (int i = tid; i < 882; i += 256) {
        ((float*)(sm + WL_O))[i]        = dev_obs[(size_t)b0 * 882 + i];
        ((float*)(sm + WL_O + 3584))[i] = dev_obs[(size_t)(b0 + 1) * 882 + i];
    }
    if (tid < 3) {
        ((float*)(sm + WL_O))[882 + tid]        = srv_obs[b0 * 3 + tid];
        ((float*)(sm + WL_O + 3584))[882 + tid] = srv_obs[(b0 + 1) * 3 + tid];
    }
    for (int r = wid; r < 128; r += 8) {
        int gr = r >> 6, rr = r & 63;
        const float* ar = adj + (size_t)(b0 + gr) * 4096 + rr * 64;
        unsigned a0 = __ballot_sync(0xffffffffu, ar[lane] != 0.0f);
        unsigned a1 = __ballot_sync(0xffffffffu, ar[32 + lane] != 0.0f);
        if (lane == 0) {
            ((unsigned*)(sm + WH_O + 4608 + gr * 512))[rr] = a0;
            ((unsigned*)(sm + WH_O + 4608 + gr * 512))[64 + rr] = a1;
            ((float*)(sm + DINV_O + gr * 256))[rr] =
                rsqrtf(fmaxf((float)(__popc(a0) + __popc(a1)), 1.0f));
        }
    }
    __syncthreads();

    // ---- adjacency bf16 tiles + embedding -> X^T hi/lo ----
    for (int i = tid; i < 1024; i += 256) {
        int g2 = i >> 9, rr = (i >> 3) & 63, chk = i & 7;
        const unsigned* mk = (const unsigned*)(sm + WH_O + 4608 + g2 * 512);
        unsigned byte8 = ((chk < 4 ? mk[rr] : mk[64 + rr]) >> ((chk & 3) * 8)) & 0xFF;
        uint4 v; uint32_t* vp = (uint32_t*)&v;
        #pragma unroll
        for (int j = 0; j < 4; j++) {
            unsigned b2 = (byte8 >> (2 * j)) & 3;
            vp[j] = ((b2 & 1) ? 0x3F80u : 0u) | ((b2 & 2) ? 0x3F800000u : 0u);
        }
        *(uint4*)(sm + g2 * 27648 + ADJ_R + rr * ST + chk * 16) = v;
    }
    for (int it = 0; it < 16; it++) {
        int idx = tid + it * 256;
        int g2 = idx >> 11, rem = idx & 2047;
        int c = rem & 63, np = (rem >> 6) * 2;
        const float* ob = (const float*)(sm + WL_O + g2 * 3584);
        const float* dv = (const float*)(sm + DINV_O + g2 * 256);
        float e[2];
        #pragma unroll
        for (int q = 0; q < 2; q++) {
            int n = np + q; float acc;
            if (n < 63) {
                acc = b_dev[c];
                const float* o = ob + n * 14;
                #pragma unroll
                for (int k = 0; k < 14; k++) acc = fmaf(o[k], s_ew[k * 64 + c], acc);
            } else {
                acc = b_srv[c];
                #pragma unroll
                for (int k = 0; k < 3; k++) acc = fmaf(ob[882 + k], s_ew[896 + k * 64 + c], acc);
            }
            e[q] = fmaxf(acc, 0.0f) * dv[n];
        }
        uint32_t lo, hi = sp2(e[0], e[1], lo);
        *(uint32_t*)(sm + g2 * 27648 + XH_R + c * ST + np * 2) = hi;
        *(uint32_t*)(sm + g2 * 27648 + XL_R + c * ST + np * 2) = lo;
    }
    __syncthreads();

    // ---- 3 GCN layers ----
    #pragma unroll 1
    for (int L = 0; L < 3; L++) {
        {   // async-stage shared W^T hi/lo (overlaps agg MMA); bias via LDG
            const unsigned char* wh = g_WT[L][0];
            const unsigned char* wl = g_WT[L][1];
            for (int i = tid; i < 576; i += 256) {
                cpasync16(sb + WH_O + i * 16, wh + i * 16);
                cpasync16(sb + WL_O + i * 16, wl + i * 16);
            }
            CP_COMMIT();
            const float* bl = (L == 0) ? b1 : (L == 1) ? b2 : b3;
            if (tid < 64) s_bw[tid] = bl[tid];
        }
        // aggregation: D = Adj @ (XH + XL)^T  (shared-A fused)
        float acc[8][4];
        #pragma unroll
        for (int i = 0; i < 8; i++) { acc[i][0]=acc[i][1]=acc[i][2]=acc[i][3]=0.f; }
        gprod32_dualB(sb + GB + ADJ_R + m0 * ST, sb + GB + XH_R + n0 * ST,
                      sb + GB + XL_R + n0 * ST, lane, acc);
        BARG(barid);            // own-graph X reads done

        // epi1: T[r][c] = dinv[r]*D -> overwrite XH/XL
        #pragma unroll
        for (int mt = 0; mt < 2; mt++) {
            int r0 = m0 + mt * 16 + g, r1 = r0 + 8;
            float d0 = s_dinv[r0], d1 = s_dinv[r1];
            #pragma unroll
            for (int nt = 0; nt < 4; nt++) {
                int c0 = n0 + nt * 8 + c0b;
                float* a4 = acc[mt * 4 + nt];
                uint32_t lo, hi;
                hi = sp2(a4[0] * d0, a4[1] * d0, lo);
                *(uint32_t*)(sm + GB + XH_R + r0 * ST + c0 * 2) = hi;
                *(uint32_t*)(sm + GB + XL_R + r0 * ST + c0 * 2) = lo;
                hi = sp2(a4[2] * d1, a4[3] * d1, lo);
                *(uint32_t*)(sm + GB + XH_R + r1 * ST + c0 * 2) = hi;
                *(uint32_t*)(sm + GB + XL_R + r1 * ST + c0 * 2) = lo;
            }
        }
        CP_WAIT0();
        __syncthreads();        // T visible to own graph + W visible to all

        #pragma unroll
        for (int i = 0; i < 8; i++) { acc[i][0]=acc[i][1]=acc[i][2]=acc[i][3]=0.f; }
        if (L < 2) {
            // gemm (transposed out): D[c][r] = Whi·(Thi+Tlo) + Wlo·Thi
            gprod32_dualB(sb + WH_O + m0 * ST, sb + GB + XH_R + n0 * ST,
                          sb + GB + XL_R + n0 * ST, lane, acc);
            gprod32(sb + WL_O + m0 * ST, sb + GB + XH_R + n0 * ST, lane, acc);
            BARG(barid);        // own T reads done
            // epi2: X^T[c][r] = relu(D + b[c]) * dinv[r]
            #pragma unroll
            for (int mt = 0; mt < 2; mt++) {
                int cA0 = m0 + mt * 16 + g, cA1 = cA0 + 8;
                float bA0 = s_bw[cA0], bA1 = s_bw[cA1];
                #pragma unroll
                for (int nt = 0; nt < 4; nt++) {
                    int r0 = n0 + nt * 8 + c0b;
                    float da = s_dinv[r0], db = s_dinv[r0 + 1];
                    float* a4 = acc[mt * 4 + nt];
                    uint32_t lo, hi;
                    hi = sp2(fmaxf(a4[0] + bA0, 0.f) * da, fmaxf(a4[1] + bA0, 0.f) * db, lo);
                    *(uint32_t*)(sm + GB + XH_R + cA0 * ST + r0 * 2) = hi;
                    *(uint32_t*)(sm + GB + XL_R + cA0 * ST + r0 * 2) = lo;
                    hi = sp2(fmaxf(a4[2] + bA1, 0.f) * da, fmaxf(a4[3] + bA1, 0.f) * db, lo);
                    *(uint32_t*)(sm + GB + XH_R + cA1 * ST + r0 * 2) = hi;
                    *(uint32_t*)(sm + GB + XL_R + cA1 * ST + r0 * 2) = lo;
                }
            }
        } else {
            // gemm3: D[r][c] = (Thi+Tlo)·Whi + Thi·Wlo  (node-major h3)
            gprod32_dualA(sb + GB + XH_R + m0 * ST, sb + GB + XL_R + m0 * ST,
                          sb + WH_O + n0 * ST, lane, acc);
            gprod32(sb + GB + XH_R + m0 * ST, sb + WL_O + n0 * ST, lane, acc);
            BARG(barid);
            // epi3: h3 = relu(D + b[c]); hi->ADJ, lo->XH
            #pragma unroll
            for (int mt = 0; mt < 2; mt++) {
                int r0 = m0 + mt * 16 + g, r1 = r0 + 8;
                #pragma unroll
                for (int nt = 0; nt < 4; nt++) {
                    int c0 = n0 + nt * 8 + c0b;
                    float b0v = s_bw[c0], b1v = s_bw[c0 + 1];
                    float* a4 = acc[mt * 4 + nt];
                    uint32_t lo, hi;
                    hi = sp2(fmaxf(a4[0] + b0v, 0.f), fmaxf(a4[1] + b1v, 0.f), lo);
                    *(uint32_t*)(sm + GB + ADJ_R + r0 * ST + c0 * 2) = hi;
                    *(uint32_t*)(sm + GB + XH_R + r0 * ST + c0 * 2) = lo;
                    hi = sp2(fmaxf(a4[2] + b0v, 0.f), fmaxf(a4[3] + b1v, 0.f), lo);
                    *(uint32_t*)(sm + GB + ADJ_R + r1 * ST + c0 * 2) = hi;
                    *(uint32_t*)(sm + GB + XH_R + r1 * ST + c0 * 2) = lo;
                }
            }
        }
        __syncthreads();        // end of layer: W reads + epi writes settled
    }

    // ---- head: async-stage Wf1^T (both halves) + wf2; overlap with mean/u ----
    {
        const unsigned char* hh = g_Wf1T[0];
        const unsigned char* hl = g_Wf1T[1];
        for (int i = tid; i < 576; i += 256) {
            cpasync16(sb + WH_O  + i * 16, hh + i * 16);
            cpasync16(sb + WL_O  + i * 16, hl + i * 16);
            cpasync16(sb + HB1H_O + i * 16, hh + 9216 + i * 16);
            cpasync16(sb + HB1L_O + i * 16, hl + 9216 + i * 16);
        }
        if (tid < 32) cpasync16(sb + BW_O + tid * 16, (const unsigned char*)Wf2 + tid * 16);
        CP_COMMIT();
    }
    if (tid < 128) {    // mean + server row per graph
        int g2 = tid >> 6, c = tid & 63;
        const unsigned char* gbp = sm + g2 * 27648;
        float s = 0.0f;
        for (int r = 0; r < 63; r++) s += rdbf(gbp, ADJ_R, r, c) + rdbf(gbp, XH_R, r, c);
        float* mp = (float*)(sm + MP_O + g2 * 512);
        mp[c] = s * (1.0f / 63.0f);
        mp[64 + c] = rdbf(gbp, ADJ_R, 63, c) + rdbf(gbp, XH_R, 63, c);
    }
    __syncthreads();
    {   // u_g[m] = bf1 + Wf1_meanᵀ mean + Wf1_srvᵀ h3srv
        int g2 = tid >> 7, m = tid & 127;
        const float* mp = (const float*)(sm + MP_O + g2 * 512);
        float acc = bf1[m];
        #pragma unroll 4
        for (int k = 0; k < 64; k++) acc = fmaf(mp[k], Wf1[(64 + k) * 128 + m], acc);
        #pragma unroll 4
        for (int k = 0; k < 64; k++) acc = fmaf(mp[64 + k], Wf1[(128 + k) * 128 + m], acc);
        ((float*)(sm + U_O + g2 * 512))[m] = acc;
    }
    CP_WAIT0();
    __syncthreads();

    // ---- head GEMM: two halves, no mid syncs ----
    float p[4] = {0.f, 0.f, 0.f, 0.f};
    #pragma unroll 1
    for (int h = 0; h < 2; h++) {
        uint32_t hiB = sb + (h ? (uint32_t)HB1H_O : (uint32_t)WH_O);
        uint32_t loB = sb + (h ? (uint32_t)HB1L_O : (uint32_t)WL_O);
        float acc[8][4];
        #pragma unroll
        for (int i = 0; i < 8; i++) { acc[i][0]=acc[i][1]=acc[i][2]=acc[i][3]=0.f; }
        gprod32_dualA(sb + GB + ADJ_R + m0 * ST, sb + GB + XH_R + m0 * ST,
                      hiB + n0 * ST, lane, acc);
        gprod32(sb + GB + ADJ_R + m0 * ST, loB + n0 * ST, lane, acc);
        #pragma unroll
        for (int mt = 0; mt < 2; mt++)
            #pragma unroll
            for (int nt = 0; nt < 4; nt++) {
                int c0 = h * 64 + n0 + nt * 8 + c0b;
                float u0 = s_u[c0], u1 = s_u[c0 + 1], w0 = s_bw[c0], w1 = s_bw[c0 + 1];
                float* a4 = acc[mt * 4 + nt];
                p[mt*2]   = fmaf(fmaxf(a4[0] + u0, 0.f), w0, p[mt*2]);
                p[mt*2]   = fmaf(fmaxf(a4[1] + u1, 0.f), w1, p[mt*2]);
                p[mt*2+1] = fmaf(fmaxf(a4[2] + u0, 0.f), w0, p[mt*2+1]);
                p[mt*2+1] = fmaf(fmaxf(a4[3] + u1, 0.f), w1, p[mt*2+1]);
            }
    }
    __syncthreads();    // u/mean reads done before part overlay writes
    #pragma unroll
    for (int i = 0; i < 4; i++) {
        p[i] += __shfl_xor_sync(0xffffffffu, p[i], 1);
        p[i] += __shfl_xor_sync(0xffffffffu, p[i], 2);
    }
    if ((lane & 3) == 0) {
        float* part = (float*)(sm + MP_O + gi * 512) + (n0 >> 5) * 64;
        part[m0 + g]          = p[0];
        part[m0 + g + 8]      = p[1];
        part[m0 + 16 + g]     = p[2];
        part[m0 + 16 + g + 8] = p[3];
    }
    __syncthreads();
    if (tid < 128) {
        int g2 = tid >> 6, i = tid & 63;
        const float* part = (const float*)(sm + MP_O + g2 * 512);
        if (i < 63) out[(size_t)(b0 + g2) * 63 + i] = part[i] + part[64 + i] + bf2[0];
    }
}

extern "C" void kernel_launch(void* const* d_in, const int* in_sizes, int n_in,
                              void* d_out, int out_size)
{
    (void)in_sizes; (void)n_in; (void)out_size;
    cudaFuncSetAttribute(pgcn_main, cudaFuncAttributeMaxDynamicSharedMemorySize, SMEM_BYTES);
    pgcn_prep<<<64, 256>>>((const float*)d_in[7], (const float*)d_in[9],
                           (const float*)d_in[11], (const float*)d_in[13]);
    pgcn_main<<<8192, 256, SMEM_BYTES>>>(
        (const float*)d_in[0],  (const float*)d_in[1],  (const float*)d_in[2],
        (const float*)d_in[3],  (const float*)d_in[4],  (const float*)d_in[5],
        (const float*)d_in[6],  (const float*)d_in[8],  (const float*)d_in[10],
        (const float*)d_in[12], (const float*)d_in[13], (const float*)d_in[14],
        (const float*)d_in[15], (const float*)d_in[16], (float*)d_out);
}

// round 11
// speedup vs baseline: 1.3531x; 1.3531x over previous
#include <cuda_runtime.h>
#include <cuda_bf16.h>
#include <cstdint>

#define ST 144                  // row stride bytes (72 bf16): bank-rotating, 16B-aligned
#define ADJ_O 0                 // adjacency -> h3 hi
#define XH_O  9216              // X^T hi / T hi / h3 lo
#define XL_O  18432             // X^T lo / T lo
#define WH_O  27648             // W^T hi (obs scratch pre-loop; head: Wf1^T half hi)
#define WL_O  36864             // W^T lo (ew scratch pre-loop; head: Wf1^T half lo)
#define MLO_O  46080
#define MHI_O  46336
#define DINV_O 46592
#define BIAS_O 46848
#define U_O    47104
#define WF2_O  47616
#define MEAN_O 48128
#define H3S_O  48384
#define PART_O 48640            // float[2][64]
#define UPART_O 49152           // float[256] u partials
#define SMEM_BYTES 50176

static __device__ __align__(16) unsigned char g_WT[3][2][9216];   // W_L^T [n][k] hi/lo
static __device__ __align__(16) unsigned char g_Wf1T[2][18432];   // Wf1_dev^T [m][k] hi/lo

__device__ __forceinline__ uint32_t smem_u32(const void* p) {
    uint32_t a;
    asm("{ .reg .u64 t; cvta.to.shared.u64 t, %1; cvt.u32.u64 %0, t; }" : "=r"(a) : "l"(p));
    return a;
}
__device__ __forceinline__ void ldsm4(uint32_t addr, uint32_t* r) {
    asm volatile("ldmatrix.sync.aligned.m8n8.x4.shared.b16 {%0,%1,%2,%3}, [%4];"
                 : "=r"(r[0]), "=r"(r[1]), "=r"(r[2]), "=r"(r[3]) : "r"(addr));
}
__device__ __forceinline__ void mma16816(float* d, const uint32_t* a, const uint32_t* b) {
    asm volatile("mma.sync.aligned.m16n8k16.row.col.f32.bf16.bf16.f32 "
        "{%0,%1,%2,%3}, {%4,%5,%6,%7}, {%8,%9}, {%0,%1,%2,%3};"
        : "+f"(d[0]), "+f"(d[1]), "+f"(d[2]), "+f"(d[3])
        : "r"(a[0]), "r"(a[1]), "r"(a[2]), "r"(a[3]), "r"(b[0]), "r"(b[1]));
}
__device__ __forceinline__ void sp1(float v, uint16_t& h, uint16_t& l) {
    __nv_bfloat16 hb = __float2bfloat16(v);
    __nv_bfloat16 lb = __float2bfloat16(v - __bfloat162float(hb));
    h = __bfloat16_as_ushort(hb); l = __bfloat16_as_ushort(lb);
}
__device__ __forceinline__ uint32_t sp2(float a, float b, uint32_t& lo) {
    uint16_t ah, al, bh, bl; sp1(a, ah, al); sp1(b, bh, bl);
    lo = (uint32_t)al | ((uint32_t)bl << 16);
    return (uint32_t)ah | ((uint32_t)bh << 16);
}
__device__ __forceinline__ float rdbf(const unsigned char* sm, int off, int r, int c) {
    return __bfloat162float(*(const __nv_bfloat16*)(sm + off + r * ST + c * 2));
}
// D(16x32) += A @ B^T over K=64; acc = 4 n-tiles x 4
__device__ __forceinline__ void gprod(uint32_t aB, uint32_t bB, int lane, float (*acc)[4]) {
    const int arow = lane & 15, acol = (lane >> 4) << 3;
    const int brow = (lane & 7) + ((lane & 16) >> 1), bcol = lane & 8;
    #pragma unroll
    for (int kk = 0; kk < 64; kk += 16) {
        uint32_t a[4]; ldsm4(aB + arow * ST + (kk + acol) * 2, a);
        #pragma unroll
        for (int nt = 0; nt < 2; nt++) {
            uint32_t bf[4]; ldsm4(bB + (nt * 16 + brow) * ST + (kk + bcol) * 2, bf);
            mma16816(acc[nt * 2], a, bf);
            mma16816(acc[nt * 2 + 1], a, bf + 2);
        }
    }
}
// acc += A@B1^T + A@B2^T (A fragments loaded once)
__device__ __forceinline__ void gprod_dualB(uint32_t aB, uint32_t b1B, uint32_t b2B,
                                            int lane, float (*acc)[4]) {
    const int arow = lane & 15, acol = (lane >> 4) << 3;
    const int brow = (lane & 7) + ((lane & 16) >> 1), bcol = lane & 8;
    #pragma unroll
    for (int kk = 0; kk < 64; kk += 16) {
        uint32_t a[4]; ldsm4(aB + arow * ST + (kk + acol) * 2, a);
        #pragma unroll
        for (int nt = 0; nt < 2; nt++) {
            uint32_t bf[4];
            ldsm4(b1B + (nt * 16 + brow) * ST + (kk + bcol) * 2, bf);
            mma16816(acc[nt * 2], a, bf);
            mma16816(acc[nt * 2 + 1], a, bf + 2);
            ldsm4(b2B + (nt * 16 + brow) * ST + (kk + bcol) * 2, bf);
            mma16816(acc[nt * 2], a, bf);
            mma16816(acc[nt * 2 + 1], a, bf + 2);
        }
    }
}
// acc += A1@B^T + A2@B^T (B fragments loaded once)
__device__ __forceinline__ void gprod_dualA(uint32_t a1B, uint32_t a2B, uint32_t bB,
                                            int lane, float (*acc)[4]) {
    const int arow = lane & 15, acol = (lane >> 4) << 3;
    const int brow = (lane & 7) + ((lane & 16) >> 1), bcol = lane & 8;
    #pragma unroll
    for (int kk = 0; kk < 64; kk += 16) {
        uint32_t a0[4], a1[4];
        ldsm4(a1B + arow * ST + (kk + acol) * 2, a0);
        ldsm4(a2B + arow * ST + (kk + acol) * 2, a1);
        #pragma unroll
        for (int nt = 0; nt < 2; nt++) {
            uint32_t bf[4]; ldsm4(bB + (nt * 16 + brow) * ST + (kk + bcol) * 2, bf);
            mma16816(acc[nt * 2], a0, bf);
            mma16816(acc[nt * 2 + 1], a0, bf + 2);
            mma16816(acc[nt * 2], a1, bf);
            mma16816(acc[nt * 2 + 1], a1, bf + 2);
        }
    }
}

__global__ void pgcn_prep(const float* __restrict__ W1, const float* __restrict__ W2,
                          const float* __restrict__ W3, const float* __restrict__ Wf1) {
    const float* Ws[3] = {W1, W2, W3};
    int gt = blockIdx.x * blockDim.x + threadIdx.x, nth = gridDim.x * blockDim.x;
    for (int L = 0; L < 3; L++)
        for (int i = gt; i < 4096; i += nth) {
            int n = i >> 6, k = i & 63;
            uint16_t h, l; sp1(Ws[L][k * 64 + n], h, l);
            *(uint16_t*)(g_WT[L][0] + n * ST + k * 2) = h;
            *(uint16_t*)(g_WT[L][1] + n * ST + k * 2) = l;
        }
    for (int i = gt; i < 8192; i += nth) {
        int m = i >> 6, k = i & 63;
        uint16_t h, l; sp1(Wf1[k * 128 + m], h, l);
        *(uint16_t*)(g_Wf1T[0] + m * ST + k * 2) = h;
        *(uint16_t*)(g_Wf1T[1] + m * ST + k * 2) = l;
    }
}

__global__ __launch_bounds__(256, 4)
void pgcn_main(const float* __restrict__ dev_obs, const float* __restrict__ srv_obs,
               const float* __restrict__ adj,
               const float* __restrict__ W_dev, const float* __restrict__ b_dev,
               const float* __restrict__ W_srv, const float* __restrict__ b_srv,
               const float* __restrict__ b1, const float* __restrict__ b2,
               const float* __restrict__ b3,
               const float* __restrict__ Wf1, const float* __restrict__ bf1,
               const float* __restrict__ Wf2, const float* __restrict__ bf2,
               float* __restrict__ out)
{
    extern __shared__ __align__(16) unsigned char sm[];
    const uint32_t sb = smem_u32(sm);
    unsigned* s_mlo = (unsigned*)(sm + MLO_O);
    unsigned* s_mhi = (unsigned*)(sm + MHI_O);
    float* s_dinv = (float*)(sm + DINV_O);
    float* s_bias = (float*)(sm + BIAS_O);
    float* s_u    = (float*)(sm + U_O);
    float* s_wf2  = (float*)(sm + WF2_O);
    float* s_mean = (float*)(sm + MEAN_O);
    float* s_h3s  = (float*)(sm + H3S_O);
    float* s_part = (float*)(sm + PART_O);
    float* s_up   = (float*)(sm + UPART_O);

    const int tid = threadIdx.x, lane = tid & 31, wid = tid >> 5;
    const int b = blockIdx.x;
    const int m0 = (wid & 3) * 16, ch2 = wid >> 2, n0 = ch2 * 32;
    const int g = lane >> 2, c0b = (lane & 3) * 2;

    // ---- stage obs (WH scratch) + emb weights (WL scratch), masks + dinv ----
    float* s_obs = (float*)(sm + WH_O);
    float* s_ew  = (float*)(sm + WL_O);
    for (int i = tid; i < 882; i += 256) s_obs[i] = dev_obs[(size_t)b * 882 + i];
    if (tid < 3) s_obs[882 + tid] = srv_obs[b * 3 + tid];
    for (int i = tid; i < 896; i += 256) s_ew[i] = W_dev[i];
    if (tid < 192) s_ew[896 + tid] = W_srv[tid];
    {
        const float* ar = adj + (size_t)b * 4096;
        for (int r = wid; r < 64; r += 8) {
            unsigned a0 = __ballot_sync(0xffffffffu, ar[r * 64 + lane] != 0.0f);
            unsigned a1 = __ballot_sync(0xffffffffu, ar[r * 64 + 32 + lane] != 0.0f);
            if (lane == 0) {
                s_mlo[r] = a0; s_mhi[r] = a1;
                s_dinv[r] = rsqrtf(fmaxf((float)(__popc(a0) + __popc(a1)), 1.0f));
            }
        }
    }
    __syncthreads();

    // ---- adjacency bf16 tile + embedding -> X^T [c][n]*dinv[n] hi/lo ----
    for (int i = tid; i < 512; i += 256) {
        int r = i >> 3, chk = i & 7;
        unsigned byte8 = ((chk < 4 ? s_mlo[r] : s_mhi[r]) >> ((chk & 3) * 8)) & 0xFF;
        uint4 v; uint32_t* vp = (uint32_t*)&v;
        #pragma unroll
        for (int j = 0; j < 4; j++) {
            unsigned b2 = (byte8 >> (2 * j)) & 3;
            vp[j] = ((b2 & 1) ? 0x3F80u : 0u) | ((b2 & 2) ? 0x3F800000u : 0u);
        }
        *(uint4*)(sm + ADJ_O + r * ST + chk * 16) = v;
    }
    for (int it = 0; it < 8; it++) {
        int idx = tid + it * 256, c = idx & 63, nn0 = (idx >> 6) * 2;
        float e[2];
        #pragma unroll
        for (int q = 0; q < 2; q++) {
            int n = nn0 + q; float acc;
            if (n < 63) {
                acc = b_dev[c];
                const float* o = s_obs + n * 14;
                #pragma unroll
                for (int k = 0; k < 14; k++) acc = fmaf(o[k], s_ew[k * 64 + c], acc);
            } else {
                acc = b_srv[c];
                #pragma unroll
                for (int k = 0; k < 3; k++) acc = fmaf(s_obs[882 + k], s_ew[896 + k * 64 + c], acc);
            }
            e[q] = fmaxf(acc, 0.0f) * s_dinv[n];
        }
        uint32_t lo, hi = sp2(e[0], e[1], lo);
        *(uint32_t*)(sm + XH_O + c * ST + nn0 * 2) = hi;
        *(uint32_t*)(sm + XL_O + c * ST + nn0 * 2) = lo;
    }
    __syncthreads();

    // ---- 3 GCN layers ----
    #pragma unroll 1
    for (int L = 0; L < 3; L++) {
        {   // stage W^T hi/lo + bias
            const uint4* wh = (const uint4*)g_WT[L][0];
            const uint4* wl = (const uint4*)g_WT[L][1];
            for (int i = tid; i < 576; i += 256) {
                ((uint4*)(sm + WH_O))[i] = wh[i];
                ((uint4*)(sm + WL_O))[i] = wl[i];
            }
            const float* bl = (L == 0) ? b1 : (L == 1) ? b2 : b3;
            if (tid < 64) s_bias[tid] = bl[tid];
        }
        // aggregation: D[r][c] = Adj @ (XH + XL)^T  (A fragments shared)
        float acc[4][4];
        #pragma unroll
        for (int i = 0; i < 4; i++) { acc[i][0]=acc[i][1]=acc[i][2]=acc[i][3]=0.f; }
        gprod_dualB(sb + ADJ_O + m0 * ST, sb + XH_O + n0 * ST, sb + XL_O + n0 * ST, lane, acc);
        __syncthreads();   // all X reads done; W staged

        // epi1: T[r][c] = dinv[r]*D -> overwrite XH/XL (T tiles)
        {
            const int r0 = m0 + g, r1 = r0 + 8;
            float d0 = s_dinv[r0], d1 = s_dinv[r1];
            #pragma unroll
            for (int nt = 0; nt < 4; nt++) {
                int c0 = n0 + nt * 8 + c0b;
                uint32_t lo, hi;
                hi = sp2(acc[nt][0] * d0, acc[nt][1] * d0, lo);
                *(uint32_t*)(sm + XH_O + r0 * ST + c0 * 2) = hi;
                *(uint32_t*)(sm + XL_O + r0 * ST + c0 * 2) = lo;
                hi = sp2(acc[nt][2] * d1, acc[nt][3] * d1, lo);
                *(uint32_t*)(sm + XH_O + r1 * ST + c0 * 2) = hi;
                *(uint32_t*)(sm + XL_O + r1 * ST + c0 * 2) = lo;
            }
        }
        __syncthreads();   // T visible

        #pragma unroll
        for (int i = 0; i < 4; i++) { acc[i][0]=acc[i][1]=acc[i][2]=acc[i][3]=0.f; }
        if (L < 2) {
            // gemm (transposed out): D[c][r] = Whi·(Thi+Tlo) + Wlo·Thi
            gprod_dualB(sb + WH_O + m0 * ST, sb + XH_O + n0 * ST, sb + XL_O + n0 * ST, lane, acc);
            gprod(sb + WL_O + m0 * ST, sb + XH_O + n0 * ST, lane, acc);
            __syncthreads();   // all T reads done
            // epi2: X^T[c][r] = relu(D + b[c]) * dinv[r], packed along r
            const int cA0 = m0 + g, cA1 = cA0 + 8;
            float bA0 = s_bias[cA0], bA1 = s_bias[cA1];
            #pragma unroll
            for (int nt = 0; nt < 4; nt++) {
                int r0 = n0 + nt * 8 + c0b;
                float da = s_dinv[r0], db = s_dinv[r0 + 1];
                uint32_t lo, hi;
                hi = sp2(fmaxf(acc[nt][0] + bA0, 0.f) * da,
                         fmaxf(acc[nt][1] + bA0, 0.f) * db, lo);
                *(uint32_t*)(sm + XH_O + cA0 * ST + r0 * 2) = hi;
                *(uint32_t*)(sm + XL_O + cA0 * ST + r0 * 2) = lo;
                hi = sp2(fmaxf(acc[nt][2] + bA1, 0.f) * da,
                         fmaxf(acc[nt][3] + bA1, 0.f) * db, lo);
                *(uint32_t*)(sm + XH_O + cA1 * ST + r0 * 2) = hi;
                *(uint32_t*)(sm + XL_O + cA1 * ST + r0 * 2) = lo;
            }
        } else {
            // gemm3: D[r][c] = (Thi+Tlo)·Whi + Thi·Wlo  (node-major h3)
            gprod_dualA(sb + XH_O + m0 * ST, sb + XL_O + m0 * ST, sb + WH_O + n0 * ST, lane, acc);
            gprod(sb + XH_O + m0 * ST, sb + WL_O + n0 * ST, lane, acc);
            __syncthreads();
            // epi3: h3 = relu(D + b[c]); hi->ADJ, lo->XH
            const int r0 = m0 + g, r1 = r0 + 8;
            #pragma unroll
            for (int nt = 0; nt < 4; nt++) {
                int c0 = n0 + nt * 8 + c0b;
                float b0v = s_bias[c0], b1v = s_bias[c0 + 1];
                uint32_t lo, hi;
                hi = sp2(fmaxf(acc[nt][0] + b0v, 0.f), fmaxf(acc[nt][1] + b1v, 0.f), lo);
                *(uint32_t*)(sm + ADJ_O + r0 * ST + c0 * 2) = hi;
                *(uint32_t*)(sm + XH_O + r0 * ST + c0 * 2) = lo;
                hi = sp2(fmaxf(acc[nt][2] + b0v, 0.f), fmaxf(acc[nt][3] + b1v, 0.f), lo);
                *(uint32_t*)(sm + ADJ_O + r1 * ST + c0 * 2) = hi;
                *(uint32_t*)(sm + XH_O + r1 * ST + c0 * 2) = lo;
            }
        }
        __syncthreads();
    }

    // ---- head prep: mean + server row || stage Wf1^T half 0 + wf2 ----
    if (tid < 64) {
        float s = 0.0f;
        for (int r = 0; r < 63; r++) s += rdbf(sm, ADJ_O, r, tid) + rdbf(sm, XH_O, r, tid);
        s_mean[tid] = s * (1.0f / 63.0f);
        s_h3s[tid] = rdbf(sm, ADJ_O, 63, tid) + rdbf(sm, XH_O, 63, tid);
    } else {
        const uint4* hh = (const uint4*)g_Wf1T[0];
        const uint4* hl = (const uint4*)g_Wf1T[1];
        for (int i = tid - 64; i < 576; i += 192) {
            ((uint4*)(sm + WH_O))[i] = hh[i];
            ((uint4*)(sm + WL_O))[i] = hl[i];
        }
        if (tid - 64 < 128) s_wf2[tid - 64] = Wf2[tid - 64];
    }
    __syncthreads();
    {   // u partials: each of 256 threads does half the k-range for one m
        int m = tid & 127, half = tid >> 7, k0 = half * 32;
        float acc = 0.0f;
        #pragma unroll 4
        for (int k = k0; k < k0 + 32; k++) acc = fmaf(s_mean[k], Wf1[(64 + k) * 128 + m], acc);
        #pragma unroll 4
        for (int k = k0; k < k0 + 32; k++) acc = fmaf(s_h3s[k], Wf1[(128 + k) * 128 + m], acc);
        s_up[tid] = acc;
    }
    __syncthreads();
    if (tid < 128) s_u[tid] = bf1[tid] + s_up[tid] + s_up[128 + tid];
    __syncthreads();

    // ---- head GEMM: two half passes over Wf1ᵀ (64 m-cols each) ----
    float p0 = 0.f, p1 = 0.f;
    #pragma unroll 1
    for (int h = 0; h < 2; h++) {
        if (h == 1) {   // restage half 1
            const uint4* hh = (const uint4*)(g_Wf1T[0] + 64 * ST);
            const uint4* hl = (const uint4*)(g_Wf1T[1] + 64 * ST);
            for (int i = tid; i < 576; i += 256) {
                ((uint4*)(sm + WH_O))[i] = hh[i];
                ((uint4*)(sm + WL_O))[i] = hl[i];
            }
            __syncthreads();
        }
        float acc[4][4];
        #pragma unroll
        for (int i = 0; i < 4; i++) { acc[i][0]=acc[i][1]=acc[i][2]=acc[i][3]=0.f; }
        gprod_dualA(sb + ADJ_O + m0 * ST, sb + XH_O + m0 * ST, sb + WH_O + n0 * ST, lane, acc);
        gprod(sb + ADJ_O + m0 * ST, sb + WL_O + n0 * ST, lane, acc);
        #pragma unroll
        for (int nt = 0; nt < 4; nt++) {
            int c0 = h * 64 + n0 + nt * 8 + c0b;
            float u0 = s_u[c0], u1 = s_u[c0 + 1], w0 = s_wf2[c0], w1 = s_wf2[c0 + 1];
            p0 = fmaf(fmaxf(acc[nt][0] + u0, 0.f), w0, p0);
            p0 = fmaf(fmaxf(acc[nt][1] + u1, 0.f), w1, p0);
            p1 = fmaf(fmaxf(acc[nt][2] + u0, 0.f), w0, p1);
            p1 = fmaf(fmaxf(acc[nt][3] + u1, 0.f), w1, p1);
        }
        __syncthreads();   // half reads done (safe to restage / finish)
    }
    p0 += __shfl_xor_sync(0xffffffffu, p0, 1); p0 += __shfl_xor_sync(0xffffffffu, p0, 2);
    p1 += __shfl_xor_sync(0xffffffffu, p1, 1); p1 += __shfl_xor_sync(0xffffffffu, p1, 2);
    if ((lane & 3) == 0) {
        s_part[ch2 * 64 + m0 + g] = p0;
        s_part[ch2 * 64 + m0 + g + 8] = p1;
    }
    __syncthreads();
    if (tid < 63) out[(size_t)b * 63 + tid] = s_part[tid] + s_part[64 + tid] + bf2[0];
}

extern "C" void kernel_launch(void* const* d_in, const int* in_sizes, int n_in,
                              void* d_out, int out_size)
{
    (void)in_sizes; (void)n_in; (void)out_size;
    cudaFuncSetAttribute(pgcn_main, cudaFuncAttributeMaxDynamicSharedMemorySize, SMEM_BYTES);
    pgcn_prep<<<64, 256>>>((const float*)d_in[7], (const float*)d_in[9],
                           (const float*)d_in[11], (const float*)d_in[13]);
    pgcn_main<<<16384, 256, SMEM_BYTES>>>(
        (const float*)d_in[0],  (const float*)d_in[1],  (const float*)d_in[2],
        (const float*)d_in[3],  (const float*)d_in[4],  (const float*)d_in[5],
        (const float*)d_in[6],  (const float*)d_in[8],  (const float*)d_in[10],
        (const float*)d_in[12], (const float*)d_in[13], (const float*)d_in[14],
        (const float*)d_in[15], (const float*)d_in[16], (float*)d_out);
}

// round 12
// speedup vs baseline: 1.3947x; 1.0307x over previous
#include <cuda_runtime.h>
#include <cuda_bf16.h>
#include <cstdint>

#define ST 144                  // row stride bytes (72 bf16): bank-rotating, 16B-aligned
#define ADJ_O 0                 // adjacency -> h3 hi
#define XH_O  9216              // X^T hi / T hi / h3 lo
#define XL_O  18432             // X^T lo / T lo / head: Wf1^T half1 hi
#define WH_O  27648             // W^T hi (obs scratch pre-loop; head: Wf1^T half0 hi -> half1 lo)
#define WL_O  36864             // W^T lo (ew scratch pre-loop; head: Wf1^T half0 lo)
#define MLO_O  46080
#define MHI_O  46336
#define DINV_O 46592
#define BIAS_O 46848
#define U_O    47104
#define WF2_O  47616
#define MEAN_O 48128
#define H3S_O  48384
#define PART_O 48640            // float[2][64]
#define CS_O   49152            // float[4][64] col-sums -> (overlay) float[256] u partials
#define SMEM_BYTES 50176

static __device__ __align__(16) unsigned char g_WT[3][2][9216];   // W_L^T [n][k] hi/lo
static __device__ __align__(16) unsigned char g_Wf1T[2][18432];   // Wf1_dev^T [m][k] hi/lo

__device__ __forceinline__ uint32_t smem_u32(const void* p) {
    uint32_t a;
    asm("{ .reg .u64 t; cvta.to.shared.u64 t, %1; cvt.u32.u64 %0, t; }" : "=r"(a) : "l"(p));
    return a;
}
__device__ __forceinline__ void ldsm4(uint32_t addr, uint32_t* r) {
    asm volatile("ldmatrix.sync.aligned.m8n8.x4.shared.b16 {%0,%1,%2,%3}, [%4];"
                 : "=r"(r[0]), "=r"(r[1]), "=r"(r[2]), "=r"(r[3]) : "r"(addr));
}
__device__ __forceinline__ void mma16816(float* d, const uint32_t* a, const uint32_t* b) {
    asm volatile("mma.sync.aligned.m16n8k16.row.col.f32.bf16.bf16.f32 "
        "{%0,%1,%2,%3}, {%4,%5,%6,%7}, {%8,%9}, {%0,%1,%2,%3};"
        : "+f"(d[0]), "+f"(d[1]), "+f"(d[2]), "+f"(d[3])
        : "r"(a[0]), "r"(a[1]), "r"(a[2]), "r"(a[3]), "r"(b[0]), "r"(b[1]));
}
__device__ __forceinline__ void sp1(float v, uint16_t& h, uint16_t& l) {
    __nv_bfloat16 hb = __float2bfloat16(v);
    __nv_bfloat16 lb = __float2bfloat16(v - __bfloat162float(hb));
    h = __bfloat16_as_ushort(hb); l = __bfloat16_as_ushort(lb);
}
__device__ __forceinline__ uint32_t sp2(float a, float b, uint32_t& lo) {
    uint16_t ah, al, bh, bl; sp1(a, ah, al); sp1(b, bh, bl);
    lo = (uint32_t)al | ((uint32_t)bl << 16);
    return (uint32_t)ah | ((uint32_t)bh << 16);
}
// D(16x32) += A @ B^T over K=64; acc = 4 n-tiles x 4
__device__ __forceinline__ void gprod(uint32_t aB, uint32_t bB, int lane, float (*acc)[4]) {
    const int arow = lane & 15, acol = (lane >> 4) << 3;
    const int brow = (lane & 7) + ((lane & 16) >> 1), bcol = lane & 8;
    #pragma unroll
    for (int kk = 0; kk < 64; kk += 16) {
        uint32_t a[4]; ldsm4(aB + arow * ST + (kk + acol) * 2, a);
        #pragma unroll
        for (int nt = 0; nt < 2; nt++) {
            uint32_t bf[4]; ldsm4(bB + (nt * 16 + brow) * ST + (kk + bcol) * 2, bf);
            mma16816(acc[nt * 2], a, bf);
            mma16816(acc[nt * 2 + 1], a, bf + 2);
        }
    }
}
// acc += A@B1^T + A@B2^T (A fragments loaded once)
__device__ __forceinline__ void gprod_dualB(uint32_t aB, uint32_t b1B, uint32_t b2B,
                                            int lane, float (*acc)[4]) {
    const int arow = lane & 15, acol = (lane >> 4) << 3;
    const int brow = (lane & 7) + ((lane & 16) >> 1), bcol = lane & 8;
    #pragma unroll
    for (int kk = 0; kk < 64; kk += 16) {
        uint32_t a[4]; ldsm4(aB + arow * ST + (kk + acol) * 2, a);
        #pragma unroll
        for (int nt = 0; nt < 2; nt++) {
            uint32_t bf[4];
            ldsm4(b1B + (nt * 16 + brow) * ST + (kk + bcol) * 2, bf);
            mma16816(acc[nt * 2], a, bf);
            mma16816(acc[nt * 2 + 1], a, bf + 2);
            ldsm4(b2B + (nt * 16 + brow) * ST + (kk + bcol) * 2, bf);
            mma16816(acc[nt * 2], a, bf);
            mma16816(acc[nt * 2 + 1], a, bf + 2);
        }
    }
}
// acc += A1@B^T + A2@B^T (B fragments loaded once)
__device__ __forceinline__ void gprod_dualA(uint32_t a1B, uint32_t a2B, uint32_t bB,
                                            int lane, float (*acc)[4]) {
    const int arow = lane & 15, acol = (lane >> 4) << 3;
    const int brow = (lane & 7) + ((lane & 16) >> 1), bcol = lane & 8;
    #pragma unroll
    for (int kk = 0; kk < 64; kk += 16) {
        uint32_t a0[4], a1[4];
        ldsm4(a1B + arow * ST + (kk + acol) * 2, a0);
        ldsm4(a2B + arow * ST + (kk + acol) * 2, a1);
        #pragma unroll
        for (int nt = 0; nt < 2; nt++) {
            uint32_t bf[4]; ldsm4(bB + (nt * 16 + brow) * ST + (kk + bcol) * 2, bf);
            mma16816(acc[nt * 2], a0, bf);
            mma16816(acc[nt * 2 + 1], a0, bf + 2);
            mma16816(acc[nt * 2], a1, bf);
            mma16816(acc[nt * 2 + 1], a1, bf + 2);
        }
    }
}

__global__ void pgcn_prep(const float* __restrict__ W1, const float* __restrict__ W2,
                          const float* __restrict__ W3, const float* __restrict__ Wf1) {
    const float* Ws[3] = {W1, W2, W3};
    int gt = blockIdx.x * blockDim.x + threadIdx.x, nth = gridDim.x * blockDim.x;
    for (int L = 0; L < 3; L++)
        for (int i = gt; i < 4096; i += nth) {
            int n = i >> 6, k = i & 63;
            uint16_t h, l; sp1(Ws[L][k * 64 + n], h, l);
            *(uint16_t*)(g_WT[L][0] + n * ST + k * 2) = h;
            *(uint16_t*)(g_WT[L][1] + n * ST + k * 2) = l;
        }
    for (int i = gt; i < 8192; i += nth) {
        int m = i >> 6, k = i & 63;
        uint16_t h, l; sp1(Wf1[k * 128 + m], h, l);
        *(uint16_t*)(g_Wf1T[0] + m * ST + k * 2) = h;
        *(uint16_t*)(g_Wf1T[1] + m * ST + k * 2) = l;
    }
}

__global__ __launch_bounds__(256, 4)
void pgcn_main(const float* __restrict__ dev_obs, const float* __restrict__ srv_obs,
               const float* __restrict__ adj,
               const float* __restrict__ W_dev, const float* __restrict__ b_dev,
               const float* __restrict__ W_srv, const float* __restrict__ b_srv,
               const float* __restrict__ b1, const float* __restrict__ b2,
               const float* __restrict__ b3,
               const float* __restrict__ Wf1, const float* __restrict__ bf1,
               const float* __restrict__ Wf2, const float* __restrict__ bf2,
               float* __restrict__ out)
{
    extern __shared__ __align__(16) unsigned char sm[];
    const uint32_t sb = smem_u32(sm);
    unsigned* s_mlo = (unsigned*)(sm + MLO_O);
    unsigned* s_mhi = (unsigned*)(sm + MHI_O);
    float* s_dinv = (float*)(sm + DINV_O);
    float* s_bias = (float*)(sm + BIAS_O);
    float* s_u    = (float*)(sm + U_O);
    float* s_wf2  = (float*)(sm + WF2_O);
    float* s_mean = (float*)(sm + MEAN_O);
    float* s_h3s  = (float*)(sm + H3S_O);
    float* s_part = (float*)(sm + PART_O);
    float* s_cs   = (float*)(sm + CS_O);    // col-sums, later u partials

    const int tid = threadIdx.x, lane = tid & 31, wid = tid >> 5;
    const int b = blockIdx.x;
    const int m0 = (wid & 3) * 16, ch2 = wid >> 2, n0 = ch2 * 32;
    const int g = lane >> 2, c0b = (lane & 3) * 2;

    // ---- stage obs (WH scratch) + emb weights (WL scratch), masks + dinv ----
    float* s_obs = (float*)(sm + WH_O);
    float* s_ew  = (float*)(sm + WL_O);
    for (int i = tid; i < 882; i += 256) s_obs[i] = dev_obs[(size_t)b * 882 + i];
    if (tid < 3) s_obs[882 + tid] = srv_obs[b * 3 + tid];
    for (int i = tid; i < 896; i += 256) s_ew[i] = W_dev[i];
    if (tid < 192) s_ew[896 + tid] = W_srv[tid];
    {
        const float* ar = adj + (size_t)b * 4096;
        for (int r = wid; r < 64; r += 8) {
            unsigned a0 = __ballot_sync(0xffffffffu, ar[r * 64 + lane] != 0.0f);
            unsigned a1 = __ballot_sync(0xffffffffu, ar[r * 64 + 32 + lane] != 0.0f);
            if (lane == 0) {
                s_mlo[r] = a0; s_mhi[r] = a1;
                s_dinv[r] = rsqrtf(fmaxf((float)(__popc(a0) + __popc(a1)), 1.0f));
            }
        }
    }
    __syncthreads();

    // ---- adjacency bf16 tile + embedding -> X^T [c][n]*dinv[n] hi/lo ----
    for (int i = tid; i < 512; i += 256) {
        int r = i >> 3, chk = i & 7;
        unsigned byte8 = ((chk < 4 ? s_mlo[r] : s_mhi[r]) >> ((chk & 3) * 8)) & 0xFF;
        uint4 v; uint32_t* vp = (uint32_t*)&v;
        #pragma unroll
        for (int j = 0; j < 4; j++) {
            unsigned b2 = (byte8 >> (2 * j)) & 3;
            vp[j] = ((b2 & 1) ? 0x3F80u : 0u) | ((b2 & 2) ? 0x3F800000u : 0u);
        }
        *(uint4*)(sm + ADJ_O + r * ST + chk * 16) = v;
    }
    for (int it = 0; it < 8; it++) {
        int idx = tid + it * 256, c = idx & 63, nn0 = (idx >> 6) * 2;
        float e[2];
        #pragma unroll
        for (int q = 0; q < 2; q++) {
            int n = nn0 + q; float acc;
            if (n < 63) {
                acc = b_dev[c];
                const float* o = s_obs + n * 14;
                #pragma unroll
                for (int k = 0; k < 14; k++) acc = fmaf(o[k], s_ew[k * 64 + c], acc);
            } else {
                acc = b_srv[c];
                #pragma unroll
                for (int k = 0; k < 3; k++) acc = fmaf(s_obs[882 + k], s_ew[896 + k * 64 + c], acc);
            }
            e[q] = fmaxf(acc, 0.0f) * s_dinv[n];
        }
        uint32_t lo, hi = sp2(e[0], e[1], lo);
        *(uint32_t*)(sm + XH_O + c * ST + nn0 * 2) = hi;
        *(uint32_t*)(sm + XL_O + c * ST + nn0 * 2) = lo;
    }
    __syncthreads();

    // ---- 3 GCN layers ----
    #pragma unroll 1
    for (int L = 0; L < 3; L++) {
        {   // stage W^T hi/lo + bias
            const uint4* wh = (const uint4*)g_WT[L][0];
            const uint4* wl = (const uint4*)g_WT[L][1];
            for (int i = tid; i < 576; i += 256) {
                ((uint4*)(sm + WH_O))[i] = wh[i];
                ((uint4*)(sm + WL_O))[i] = wl[i];
            }
            const float* bl = (L == 0) ? b1 : (L == 1) ? b2 : b3;
            if (tid < 64) s_bias[tid] = bl[tid];
        }
        // aggregation: D[r][c] = Adj @ (XH + XL)^T  (A fragments shared)
        float acc[4][4];
        #pragma unroll
        for (int i = 0; i < 4; i++) { acc[i][0]=acc[i][1]=acc[i][2]=acc[i][3]=0.f; }
        gprod_dualB(sb + ADJ_O + m0 * ST, sb + XH_O + n0 * ST, sb + XL_O + n0 * ST, lane, acc);
        __syncthreads();   // all X reads done; W staged

        // epi1: T[r][c] = dinv[r]*D -> overwrite XH/XL (T tiles)
        {
            const int r0 = m0 + g, r1 = r0 + 8;
            float d0 = s_dinv[r0], d1 = s_dinv[r1];
            #pragma unroll
            for (int nt = 0; nt < 4; nt++) {
                int c0 = n0 + nt * 8 + c0b;
                uint32_t lo, hi;
                hi = sp2(acc[nt][0] * d0, acc[nt][1] * d0, lo);
                *(uint32_t*)(sm + XH_O + r0 * ST + c0 * 2) = hi;
                *(uint32_t*)(sm + XL_O + r0 * ST + c0 * 2) = lo;
                hi = sp2(acc[nt][2] * d1, acc[nt][3] * d1, lo);
                *(uint32_t*)(sm + XH_O + r1 * ST + c0 * 2) = hi;
                *(uint32_t*)(sm + XL_O + r1 * ST + c0 * 2) = lo;
            }
        }
        __syncthreads();   // T visible

        #pragma unroll
        for (int i = 0; i < 4; i++) { acc[i][0]=acc[i][1]=acc[i][2]=acc[i][3]=0.f; }
        if (L < 2) {
            // gemm (transposed out): D[c][r] = Whi·(Thi+Tlo) + Wlo·Thi
            gprod_dualB(sb + WH_O + m0 * ST, sb + XH_O + n0 * ST, sb + XL_O + n0 * ST, lane, acc);
            gprod(sb + WL_O + m0 * ST, sb + XH_O + n0 * ST, lane, acc);
            __syncthreads();   // all T reads done
            // epi2: X^T[c][r] = relu(D + b[c]) * dinv[r], packed along r
            const int cA0 = m0 + g, cA1 = cA0 + 8;
            float bA0 = s_bias[cA0], bA1 = s_bias[cA1];
            #pragma unroll
            for (int nt = 0; nt < 4; nt++) {
                int r0 = n0 + nt * 8 + c0b;
                float da = s_dinv[r0], db = s_dinv[r0 + 1];
                uint32_t lo, hi;
                hi = sp2(fmaxf(acc[nt][0] + bA0, 0.f) * da,
                         fmaxf(acc[nt][1] + bA0, 0.f) * db, lo);
                *(uint32_t*)(sm + XH_O + cA0 * ST + r0 * 2) = hi;
                *(uint32_t*)(sm + XL_O + cA0 * ST + r0 * 2) = lo;
                hi = sp2(fmaxf(acc[nt][2] + bA1, 0.f) * da,
                         fmaxf(acc[nt][3] + bA1, 0.f) * db, lo);
                *(uint32_t*)(sm + XH_O + cA1 * ST + r0 * 2) = hi;
                *(uint32_t*)(sm + XL_O + cA1 * ST + r0 * 2) = lo;
            }
        } else {
            // gemm3: D[r][c] = (Thi+Tlo)·Whi + Thi·Wlo  (node-major h3)
            gprod_dualA(sb + XH_O + m0 * ST, sb + XL_O + m0 * ST, sb + WH_O + n0 * ST, lane, acc);
            gprod(sb + XH_O + m0 * ST, sb + WL_O + n0 * ST, lane, acc);
            __syncthreads();
            // epi3: h3 = relu(D + b[c]); hi->ADJ, lo->XH; col-sums + server row
            const int r0 = m0 + g, r1 = r0 + 8;
            const bool srvlane = (m0 == 48) && (g == 7);   // r1 == 63
            float csA[4], csB[4];
            #pragma unroll
            for (int nt = 0; nt < 4; nt++) {
                int c0 = n0 + nt * 8 + c0b;
                float b0v = s_bias[c0], b1v = s_bias[c0 + 1];
                float v0 = fmaxf(acc[nt][0] + b0v, 0.f);
                float v1 = fmaxf(acc[nt][1] + b1v, 0.f);
                float v2 = fmaxf(acc[nt][2] + b0v, 0.f);
                float v3 = fmaxf(acc[nt][3] + b1v, 0.f);
                uint32_t lo, hi;
                hi = sp2(v0, v1, lo);
                *(uint32_t*)(sm + ADJ_O + r0 * ST + c0 * 2) = hi;
                *(uint32_t*)(sm + XH_O + r0 * ST + c0 * 2) = lo;
                hi = sp2(v2, v3, lo);
                *(uint32_t*)(sm + ADJ_O + r1 * ST + c0 * 2) = hi;
                *(uint32_t*)(sm + XH_O + r1 * ST + c0 * 2) = lo;
                csA[nt] = v0 + (srvlane ? 0.f : v2);
                csB[nt] = v1 + (srvlane ? 0.f : v3);
                if (srvlane) { s_h3s[c0] = v2; s_h3s[c0 + 1] = v3; }
            }
            #pragma unroll
            for (int off = 4; off < 32; off <<= 1) {
                #pragma unroll
                for (int nt = 0; nt < 4; nt++) {
                    csA[nt] += __shfl_xor_sync(0xffffffffu, csA[nt], off);
                    csB[nt] += __shfl_xor_sync(0xffffffffu, csB[nt], off);
                }
            }
            if (g == 0) {   // lanes 0..3 publish per-m-tile column sums
                float* cs = s_cs + (m0 >> 4) * 64;
                #pragma unroll
                for (int nt = 0; nt < 4; nt++) {
                    int c0 = n0 + nt * 8 + c0b;
                    cs[c0] = csA[nt]; cs[c0 + 1] = csB[nt];
                }
            }
        }
        __syncthreads();
    }

    // ---- P1: mean from col-sums (tid<64) || stage Wf1^T half0 hi/lo + half1 hi + wf2 ----
    if (tid < 64) {
        s_mean[tid] = (s_cs[tid] + s_cs[64 + tid] + s_cs[128 + tid] + s_cs[192 + tid])
                      * (1.0f / 63.0f);
    } else {
        const uint4* hh = (const uint4*)g_Wf1T[0];
        const uint4* hl = (const uint4*)g_Wf1T[1];
        for (int i = tid - 64; i < 576; i += 192) {
            ((uint4*)(sm + WH_O))[i] = hh[i];
            ((uint4*)(sm + WL_O))[i] = hl[i];
            ((uint4*)(sm + XL_O))[i] = hh[576 + i];   // half1 hi pre-staged
        }
        if (tid - 64 < 128) s_wf2[tid - 64] = Wf2[tid - 64];
    }
    __syncthreads();
    {   // u partials: each of 256 threads does half the k-range for one m (overlays s_cs)
        int m = tid & 127, half = tid >> 7, k0 = half * 32;
        float acc = 0.0f;
        #pragma unroll 4
        for (int k = k0; k < k0 + 32; k++) acc = fmaf(s_mean[k], Wf1[(64 + k) * 128 + m], acc);
        #pragma unroll 4
        for (int k = k0; k < k0 + 32; k++) acc = fmaf(s_h3s[k], Wf1[(128 + k) * 128 + m], acc);
        s_cs[tid] = acc;
    }
    __syncthreads();
    if (tid < 128) s_u[tid] = bf1[tid] + s_cs[tid] + s_cs[128 + tid];
    __syncthreads();

    // ---- head GEMM half 0 (B = WH/WL) ----
    float p0 = 0.f, p1 = 0.f;
    {
        float acc[4][4];
        #pragma unroll
        for (int i = 0; i < 4; i++) { acc[i][0]=acc[i][1]=acc[i][2]=acc[i][3]=0.f; }
        gprod_dualA(sb + ADJ_O + m0 * ST, sb + XH_O + m0 * ST, sb + WH_O + n0 * ST, lane, acc);
        gprod(sb + ADJ_O + m0 * ST, sb + WL_O + n0 * ST, lane, acc);
        #pragma unroll
        for (int nt = 0; nt < 4; nt++) {
            int c0 = n0 + nt * 8 + c0b;
            float u0 = s_u[c0], u1 = s_u[c0 + 1], w0 = s_wf2[c0], w1 = s_wf2[c0 + 1];
            p0 = fmaf(fmaxf(acc[nt][0] + u0, 0.f), w0, p0);
            p0 = fmaf(fmaxf(acc[nt][1] + u1, 0.f), w1, p0);
            p1 = fmaf(fmaxf(acc[nt][2] + u0, 0.f), w0, p1);
            p1 = fmaf(fmaxf(acc[nt][3] + u1, 0.f), w1, p1);
        }
    }
    __syncthreads();   // WH reads done
    {   // stage half1 lo into WH (only 9KB now)
        const uint4* hl = (const uint4*)(g_Wf1T[1] + 9216);
        for (int i = tid; i < 576; i += 256) ((uint4*)(sm + WH_O))[i] = hl[i];
    }
    __syncthreads();
    // ---- head GEMM half 1 (B hi = XL pre-staged, lo = WH) ----
    {
        float acc[4][4];
        #pragma unroll
        for (int i = 0; i < 4; i++) { acc[i][0]=acc[i][1]=acc[i][2]=acc[i][3]=0.f; }
        gprod_dualA(sb + ADJ_O + m0 * ST, sb + XH_O + m0 * ST, sb + XL_O + n0 * ST, lane, acc);
        gprod(sb + ADJ_O + m0 * ST, sb + WH_O + n0 * ST, lane, acc);
        #pragma unroll
        for (int nt = 0; nt < 4; nt++) {
            int c0 = 64 + n0 + nt * 8 + c0b;
            float u0 = s_u[c0], u1 = s_u[c0 + 1], w0 = s_wf2[c0], w1 = s_wf2[c0 + 1];
            p0 = fmaf(fmaxf(acc[nt][0] + u0, 0.f), w0, p0);
            p0 = fmaf(fmaxf(acc[nt][1] + u1, 0.f), w1, p0);
            p1 = fmaf(fmaxf(acc[nt][2] + u0, 0.f), w0, p1);
            p1 = fmaf(fmaxf(acc[nt][3] + u1, 0.f), w1, p1);
        }
    }
    p0 += __shfl_xor_sync(0xffffffffu, p0, 1); p0 += __shfl_xor_sync(0xffffffffu, p0, 2);
    p1 += __shfl_xor_sync(0xffffffffu, p1, 1); p1 += __shfl_xor_sync(0xffffffffu, p1, 2);
    if ((lane & 3) == 0) {
        s_part[ch2 * 64 + m0 + g] = p0;
        s_part[ch2 * 64 + m0 + g + 8] = p1;
    }
    __syncthreads();
    if (tid < 63) out[(size_t)b * 63 + tid] = s_part[tid] + s_part[64 + tid] + bf2[0];
}

extern "C" void kernel_launch(void* const* d_in, const int* in_sizes, int n_in,
                              void* d_out, int out_size)
{
    (void)in_sizes; (void)n_in; (void)out_size;
    cudaFuncSetAttribute(pgcn_main, cudaFuncAttributeMaxDynamicSharedMemorySize, SMEM_BYTES);
    pgcn_prep<<<64, 256>>>((const float*)d_in[7], (const float*)d_in[9],
                           (const float*)d_in[11], (const float*)d_in[13]);
    pgcn_main<<<16384, 256, SMEM_BYTES>>>(
        (const float*)d_in[0],  (const float*)d_in[1],  (const float*)d_in[2],
        (const float*)d_in[3],  (const float*)d_in[4],  (const float*)d_in[5],
        (const float*)d_in[6],  (const float*)d_in[8],  (const float*)d_in[10],
        (const float*)d_in[12], (const float*)d_in[13], (const float*)d_in[14],
        (const float*)d_in[15], (const float*)d_in[16], (float*)d_out);
}

// round 13
// speedup vs baseline: 1.4533x; 1.0421x over previous
#include <cuda_runtime.h>
#include <cuda_bf16.h>
#include <cstdint>

#define ST 144                  // row stride bytes (72 bf16): bank-rotating, 16B-aligned
#define ADJ_O 0                 // adjacency -> h3 hi
#define XH_O  9216              // X^T hi / T hi / h3 lo
#define XL_O  18432             // X^T lo / T lo / head: Wf1^T half1 hi
#define WH_O  27648             // W^T hi (obs scratch pre-loop; head: Wf1^T half0 hi -> half1 lo)
#define WL_O  36864             // W^T lo (ew scratch pre-loop; head: Wf1^T half0 lo)
#define MLO_O  46080
#define MHI_O  46336
#define DINV_O 46592
#define BIAS_O 46848
#define U_O    47104
#define WF2_O  47616
#define MEAN_O 48128
#define H3S_O  48384
#define PART_O 48640            // float[2][64]
#define CS_O   49152            // float[4][64] col-sums -> (overlay) float[256] u partials
#define SMEM_BYTES 50176

static __device__ __align__(16) unsigned char g_WT[3][2][9216];   // W_L^T [n][k] hi/lo
static __device__ __align__(16) unsigned char g_Wf1T[2][18432];   // Wf1_dev^T [m][k] hi/lo

__device__ __forceinline__ uint32_t smem_u32(const void* p) {
    uint32_t a;
    asm("{ .reg .u64 t; cvta.to.shared.u64 t, %1; cvt.u32.u64 %0, t; }" : "=r"(a) : "l"(p));
    return a;
}
__device__ __forceinline__ void ldsm4(uint32_t addr, uint32_t* r) {
    asm volatile("ldmatrix.sync.aligned.m8n8.x4.shared.b16 {%0,%1,%2,%3}, [%4];"
                 : "=r"(r[0]), "=r"(r[1]), "=r"(r[2]), "=r"(r[3]) : "r"(addr));
}
__device__ __forceinline__ void mma16816(float* d, const uint32_t* a, const uint32_t* b) {
    asm volatile("mma.sync.aligned.m16n8k16.row.col.f32.bf16.bf16.f32 "
        "{%0,%1,%2,%3}, {%4,%5,%6,%7}, {%8,%9}, {%0,%1,%2,%3};"
        : "+f"(d[0]), "+f"(d[1]), "+f"(d[2]), "+f"(d[3])
        : "r"(a[0]), "r"(a[1]), "r"(a[2]), "r"(a[3]), "r"(b[0]), "r"(b[1]));
}
__device__ __forceinline__ void sp1(float v, uint16_t& h, uint16_t& l) {
    __nv_bfloat16 hb = __float2bfloat16(v);
    __nv_bfloat16 lb = __float2bfloat16(v - __bfloat162float(hb));
    h = __bfloat16_as_ushort(hb); l = __bfloat16_as_ushort(lb);
}
// pack (a,b) -> hi bf16x2 (a low, b high) + residual lo bf16x2, via cvt.rn.bf16x2
__device__ __forceinline__ uint32_t sp2(float a, float b, uint32_t& lo) {
    uint32_t hi;
    asm("cvt.rn.bf16x2.f32 %0, %1, %2;" : "=r"(hi) : "f"(b), "f"(a));
    float ha = __uint_as_float(hi << 16);
    float hb = __uint_as_float(hi & 0xffff0000u);
    asm("cvt.rn.bf16x2.f32 %0, %1, %2;" : "=r"(lo) : "f"(b - hb), "f"(a - ha));
    return hi;
}
// acc += A@B1^T + A@B2^T (A fragments loaded once); D(16x32), K=64
__device__ __forceinline__ void gprod_dualB(uint32_t aB, uint32_t b1B, uint32_t b2B,
                                            int lane, float (*acc)[4]) {
    const int arow = lane & 15, acol = (lane >> 4) << 3;
    const int brow = (lane & 7) + ((lane & 16) >> 1), bcol = lane & 8;
    #pragma unroll
    for (int kk = 0; kk < 64; kk += 16) {
        uint32_t a[4]; ldsm4(aB + arow * ST + (kk + acol) * 2, a);
        #pragma unroll
        for (int nt = 0; nt < 2; nt++) {
            uint32_t bf[4];
            ldsm4(b1B + (nt * 16 + brow) * ST + (kk + bcol) * 2, bf);
            mma16816(acc[nt * 2], a, bf);
            mma16816(acc[nt * 2 + 1], a, bf + 2);
            ldsm4(b2B + (nt * 16 + brow) * ST + (kk + bcol) * 2, bf);
            mma16816(acc[nt * 2], a, bf);
            mma16816(acc[nt * 2 + 1], a, bf + 2);
        }
    }
}
// acc += A1@B1^T + A1@B2^T + A2@B1^T — all fragments loaded once (tri-fused split pass)
__device__ __forceinline__ void gprod_tri(uint32_t a1B, uint32_t a2B,
                                          uint32_t b1B, uint32_t b2B,
                                          int lane, float (*acc)[4]) {
    const int arow = lane & 15, acol = (lane >> 4) << 3;
    const int brow = (lane & 7) + ((lane & 16) >> 1), bcol = lane & 8;
    #pragma unroll
    for (int kk = 0; kk < 64; kk += 16) {
        uint32_t a0[4], a1[4];
        ldsm4(a1B + arow * ST + (kk + acol) * 2, a0);
        ldsm4(a2B + arow * ST + (kk + acol) * 2, a1);
        #pragma unroll
        for (int nt = 0; nt < 2; nt++) {
            uint32_t bf[4];
            ldsm4(b1B + (nt * 16 + brow) * ST + (kk + bcol) * 2, bf);
            mma16816(acc[nt * 2], a0, bf);
            mma16816(acc[nt * 2 + 1], a0, bf + 2);
            mma16816(acc[nt * 2], a1, bf);
            mma16816(acc[nt * 2 + 1], a1, bf + 2);
            ldsm4(b2B + (nt * 16 + brow) * ST + (kk + bcol) * 2, bf);
            mma16816(acc[nt * 2], a0, bf);
            mma16816(acc[nt * 2 + 1], a0, bf + 2);
        }
    }
}

__global__ void pgcn_prep(const float* __restrict__ W1, const float* __restrict__ W2,
                          const float* __restrict__ W3, const float* __restrict__ Wf1) {
    const float* Ws[3] = {W1, W2, W3};
    int gt = blockIdx.x * blockDim.x + threadIdx.x, nth = gridDim.x * blockDim.x;
    for (int L = 0; L < 3; L++)
        for (int i = gt; i < 4096; i += nth) {
            int n = i >> 6, k = i & 63;
            uint16_t h, l; sp1(Ws[L][k * 64 + n], h, l);
            *(uint16_t*)(g_WT[L][0] + n * ST + k * 2) = h;
            *(uint16_t*)(g_WT[L][1] + n * ST + k * 2) = l;
        }
    for (int i = gt; i < 8192; i += nth) {
        int m = i >> 6, k = i & 63;
        uint16_t h, l; sp1(Wf1[k * 128 + m], h, l);
        *(uint16_t*)(g_Wf1T[0] + m * ST + k * 2) = h;
        *(uint16_t*)(g_Wf1T[1] + m * ST + k * 2) = l;
    }
}

__global__ __launch_bounds__(256, 4)
void pgcn_main(const float* __restrict__ dev_obs, const float* __restrict__ srv_obs,
               const float* __restrict__ adj,
               const float* __restrict__ W_dev, const float* __restrict__ b_dev,
               const float* __restrict__ W_srv, const float* __restrict__ b_srv,
               const float* __restrict__ b1, const float* __restrict__ b2,
               const float* __restrict__ b3,
               const float* __restrict__ Wf1, const float* __restrict__ bf1,
               const float* __restrict__ Wf2, const float* __restrict__ bf2,
               float* __restrict__ out)
{
    extern __shared__ __align__(16) unsigned char sm[];
    const uint32_t sb = smem_u32(sm);
    unsigned* s_mlo = (unsigned*)(sm + MLO_O);
    unsigned* s_mhi = (unsigned*)(sm + MHI_O);
    float* s_dinv = (float*)(sm + DINV_O);
    float* s_bias = (float*)(sm + BIAS_O);
    float* s_u    = (float*)(sm + U_O);
    float* s_wf2  = (float*)(sm + WF2_O);
    float* s_mean = (float*)(sm + MEAN_O);
    float* s_h3s  = (float*)(sm + H3S_O);
    float* s_part = (float*)(sm + PART_O);
    float* s_cs   = (float*)(sm + CS_O);    // col-sums, later u partials

    const int tid = threadIdx.x, lane = tid & 31, wid = tid >> 5;
    const int b = blockIdx.x;
    const int m0 = (wid & 3) * 16, ch2 = wid >> 2, n0 = ch2 * 32;
    const int g = lane >> 2, c0b = (lane & 3) * 2;

    // ---- stage obs (WH scratch) + emb weights (WL scratch), masks + dinv ----
    float* s_obs = (float*)(sm + WH_O);
    float* s_ew  = (float*)(sm + WL_O);
    for (int i = tid; i < 882; i += 256) s_obs[i] = dev_obs[(size_t)b * 882 + i];
    if (tid < 3) s_obs[882 + tid] = srv_obs[b * 3 + tid];
    for (int i = tid; i < 896; i += 256) s_ew[i] = W_dev[i];
    if (tid < 192) s_ew[896 + tid] = W_srv[tid];
    {
        const float* ar = adj + (size_t)b * 4096;
        for (int r = wid; r < 64; r += 8) {
            unsigned a0 = __ballot_sync(0xffffffffu, ar[r * 64 + lane] != 0.0f);
            unsigned a1 = __ballot_sync(0xffffffffu, ar[r * 64 + 32 + lane] != 0.0f);
            if (lane == 0) {
                s_mlo[r] = a0; s_mhi[r] = a1;
                s_dinv[r] = rsqrtf(fmaxf((float)(__popc(a0) + __popc(a1)), 1.0f));
            }
        }
    }
    __syncthreads();

    // ---- adjacency bf16 tile + embedding -> X^T [c][n]*dinv[n] hi/lo ----
    for (int i = tid; i < 512; i += 256) {
        int r = i >> 3, chk = i & 7;
        unsigned byte8 = ((chk < 4 ? s_mlo[r] : s_mhi[r]) >> ((chk & 3) * 8)) & 0xFF;
        uint4 v; uint32_t* vp = (uint32_t*)&v;
        #pragma unroll
        for (int j = 0; j < 4; j++) {
            unsigned b2 = (byte8 >> (2 * j)) & 3;
            vp[j] = ((b2 & 1) ? 0x3F80u : 0u) | ((b2 & 2) ? 0x3F800000u : 0u);
        }
        *(uint4*)(sm + ADJ_O + r * ST + chk * 16) = v;
    }
    for (int it = 0; it < 8; it++) {
        int idx = tid + it * 256, c = idx & 63, nn0 = (idx >> 6) * 2;
        float e[2];
        #pragma unroll
        for (int q = 0; q < 2; q++) {
            int n = nn0 + q; float acc;
            if (n < 63) {
                acc = b_dev[c];
                const float* o = s_obs + n * 14;
                #pragma unroll
                for (int k = 0; k < 14; k++) acc = fmaf(o[k], s_ew[k * 64 + c], acc);
            } else {
                acc = b_srv[c];
                #pragma unroll
                for (int k = 0; k < 3; k++) acc = fmaf(s_obs[882 + k], s_ew[896 + k * 64 + c], acc);
            }
            e[q] = fmaxf(acc, 0.0f) * s_dinv[n];
        }
        uint32_t lo, hi = sp2(e[0], e[1], lo);
        *(uint32_t*)(sm + XH_O + c * ST + nn0 * 2) = hi;
        *(uint32_t*)(sm + XL_O + c * ST + nn0 * 2) = lo;
    }
    __syncthreads();

    // ---- 3 GCN layers ----
    #pragma unroll 1
    for (int L = 0; L < 3; L++) {
        {   // stage W^T hi/lo + bias
            const uint4* wh = (const uint4*)g_WT[L][0];
            const uint4* wl = (const uint4*)g_WT[L][1];
            for (int i = tid; i < 576; i += 256) {
                ((uint4*)(sm + WH_O))[i] = wh[i];
                ((uint4*)(sm + WL_O))[i] = wl[i];
            }
            const float* bl = (L == 0) ? b1 : (L == 1) ? b2 : b3;
            if (tid < 64) s_bias[tid] = bl[tid];
        }
        // aggregation: D[r][c] = Adj @ (XH + XL)^T  (A fragments shared)
        float acc[4][4];
        #pragma unroll
        for (int i = 0; i < 4; i++) { acc[i][0]=acc[i][1]=acc[i][2]=acc[i][3]=0.f; }
        gprod_dualB(sb + ADJ_O + m0 * ST, sb + XH_O + n0 * ST, sb + XL_O + n0 * ST, lane, acc);
        __syncthreads();   // all X reads done; W staged

        // epi1: T[r][c] = dinv[r]*D -> overwrite XH/XL (T tiles)
        {
            const int r0 = m0 + g, r1 = r0 + 8;
            float d0 = s_dinv[r0], d1 = s_dinv[r1];
            #pragma unroll
            for (int nt = 0; nt < 4; nt++) {
                int c0 = n0 + nt * 8 + c0b;
                uint32_t lo, hi;
                hi = sp2(acc[nt][0] * d0, acc[nt][1] * d0, lo);
                *(uint32_t*)(sm + XH_O + r0 * ST + c0 * 2) = hi;
                *(uint32_t*)(sm + XL_O + r0 * ST + c0 * 2) = lo;
                hi = sp2(acc[nt][2] * d1, acc[nt][3] * d1, lo);
                *(uint32_t*)(sm + XH_O + r1 * ST + c0 * 2) = hi;
                *(uint32_t*)(sm + XL_O + r1 * ST + c0 * 2) = lo;
            }
        }
        __syncthreads();   // T visible

        #pragma unroll
        for (int i = 0; i < 4; i++) { acc[i][0]=acc[i][1]=acc[i][2]=acc[i][3]=0.f; }
        if (L < 2) {
            // gemm (transposed out): D[c][r] = Whi·(Thi+Tlo) + Wlo·Thi (tri-fused)
            gprod_tri(sb + WH_O + m0 * ST, sb + WL_O + m0 * ST,
                      sb + XH_O + n0 * ST, sb + XL_O + n0 * ST, lane, acc);
            __syncthreads();   // all T reads done
            // epi2: X^T[c][r] = relu(D + b[c]) * dinv[r], packed along r
            const int cA0 = m0 + g, cA1 = cA0 + 8;
            float bA0 = s_bias[cA0], bA1 = s_bias[cA1];
            #pragma unroll
            for (int nt = 0; nt < 4; nt++) {
                int r0 = n0 + nt * 8 + c0b;
                float da = s_dinv[r0], db = s_dinv[r0 + 1];
                uint32_t lo, hi;
                hi = sp2(fmaxf(acc[nt][0] + bA0, 0.f) * da,
                         fmaxf(acc[nt][1] + bA0, 0.f) * db, lo);
                *(uint32_t*)(sm + XH_O + cA0 * ST + r0 * 2) = hi;
                *(uint32_t*)(sm + XL_O + cA0 * ST + r0 * 2) = lo;
                hi = sp2(fmaxf(acc[nt][2] + bA1, 0.f) * da,
                         fmaxf(acc[nt][3] + bA1, 0.f) * db, lo);
                *(uint32_t*)(sm + XH_O + cA1 * ST + r0 * 2) = hi;
                *(uint32_t*)(sm + XL_O + cA1 * ST + r0 * 2) = lo;
            }
        } else {
            // gemm3: D[r][c] = (Thi+Tlo)·Whi + Thi·Wlo  (node-major h3, tri-fused)
            gprod_tri(sb + XH_O + m0 * ST, sb + XL_O + m0 * ST,
                      sb + WH_O + n0 * ST, sb + WL_O + n0 * ST, lane, acc);
            __syncthreads();
            // epi3: h3 = relu(D + b[c]); hi->ADJ, lo->XH; col-sums + server row
            const int r0 = m0 + g, r1 = r0 + 8;
            const bool srvlane = (m0 == 48) && (g == 7);   // r1 == 63
            float csA[4], csB[4];
            #pragma unroll
            for (int nt = 0; nt < 4; nt++) {
                int c0 = n0 + nt * 8 + c0b;
                float b0v = s_bias[c0], b1v = s_bias[c0 + 1];
                float v0 = fmaxf(acc[nt][0] + b0v, 0.f);
                float v1 = fmaxf(acc[nt][1] + b1v, 0.f);
                float v2 = fmaxf(acc[nt][2] + b0v, 0.f);
                float v3 = fmaxf(acc[nt][3] + b1v, 0.f);
                uint32_t lo, hi;
                hi = sp2(v0, v1, lo);
                *(uint32_t*)(sm + ADJ_O + r0 * ST + c0 * 2) = hi;
                *(uint32_t*)(sm + XH_O + r0 * ST + c0 * 2) = lo;
                hi = sp2(v2, v3, lo);
                *(uint32_t*)(sm + ADJ_O + r1 * ST + c0 * 2) = hi;
                *(uint32_t*)(sm + XH_O + r1 * ST + c0 * 2) = lo;
                csA[nt] = v0 + (srvlane ? 0.f : v2);
                csB[nt] = v1 + (srvlane ? 0.f : v3);
                if (srvlane) { s_h3s[c0] = v2; s_h3s[c0 + 1] = v3; }
            }
            #pragma unroll
            for (int off = 4; off < 32; off <<= 1) {
                #pragma unroll
                for (int nt = 0; nt < 4; nt++) {
                    csA[nt] += __shfl_xor_sync(0xffffffffu, csA[nt], off);
                    csB[nt] += __shfl_xor_sync(0xffffffffu, csB[nt], off);
                }
            }
            if (g == 0) {   // lanes 0..3 publish per-m-tile column sums
                float* cs = s_cs + (m0 >> 4) * 64;
                #pragma unroll
                for (int nt = 0; nt < 4; nt++) {
                    int c0 = n0 + nt * 8 + c0b;
                    cs[c0] = csA[nt]; cs[c0 + 1] = csB[nt];
                }
            }
        }
        __syncthreads();
    }

    // ---- P1: mean from col-sums (tid<64) || stage Wf1^T half0 hi/lo + half1 hi + wf2 ----
    if (tid < 64) {
        s_mean[tid] = (s_cs[tid] + s_cs[64 + tid] + s_cs[128 + tid] + s_cs[192 + tid])
                      * (1.0f / 63.0f);
    } else {
        const uint4* hh = (const uint4*)g_Wf1T[0];
        const uint4* hl = (const uint4*)g_Wf1T[1];
        for (int i = tid - 64; i < 576; i += 192) {
            ((uint4*)(sm + WH_O))[i] = hh[i];
            ((uint4*)(sm + WL_O))[i] = hl[i];
            ((uint4*)(sm + XL_O))[i] = hh[576 + i];   // half1 hi pre-staged
        }
        if (tid - 64 < 128) s_wf2[tid - 64] = Wf2[tid - 64];
    }
    __syncthreads();
    {   // u partials: each of 256 threads does half the k-range for one m (overlays s_cs)
        int m = tid & 127, half = tid >> 7, k0 = half * 32;
        float acc = 0.0f;
        #pragma unroll 4
        for (int k = k0; k < k0 + 32; k++) acc = fmaf(s_mean[k], Wf1[(64 + k) * 128 + m], acc);
        #pragma unroll 4
        for (int k = k0; k < k0 + 32; k++) acc = fmaf(s_h3s[k], Wf1[(128 + k) * 128 + m], acc);
        s_cs[tid] = acc;
    }
    __syncthreads();
    if (tid < 128) s_u[tid] = bf1[tid] + s_cs[tid] + s_cs[128 + tid];
    __syncthreads();

    // ---- head GEMM half 0 (B = WH/WL, tri-fused) ----
    float p0 = 0.f, p1 = 0.f;
    {
        float acc[4][4];
        #pragma unroll
        for (int i = 0; i < 4; i++) { acc[i][0]=acc[i][1]=acc[i][2]=acc[i][3]=0.f; }
        gprod_tri(sb + ADJ_O + m0 * ST, sb + XH_O + m0 * ST,
                  sb + WH_O + n0 * ST, sb + WL_O + n0 * ST, lane, acc);
        #pragma unroll
        for (int nt = 0; nt < 4; nt++) {
            int c0 = n0 + nt * 8 + c0b;
            float u0 = s_u[c0], u1 = s_u[c0 + 1], w0 = s_wf2[c0], w1 = s_wf2[c0 + 1];
            p0 = fmaf(fmaxf(acc[nt][0] + u0, 0.f), w0, p0);
            p0 = fmaf(fmaxf(acc[nt][1] + u1, 0.f), w1, p0);
            p1 = fmaf(fmaxf(acc[nt][2] + u0, 0.f), w0, p1);
            p1 = fmaf(fmaxf(acc[nt][3] + u1, 0.f), w1, p1);
        }
    }
    __syncthreads();   // WH reads done
    {   // stage half1 lo into WH (only 9KB now)
        const uint4* hl = (const uint4*)(g_Wf1T[1] + 9216);
        for (int i = tid; i < 576; i += 256) ((uint4*)(sm + WH_O))[i] = hl[i];
    }
    __syncthreads();
    // ---- head GEMM half 1 (B hi = XL pre-staged, lo = WH, tri-fused) ----
    {
        float acc[4][4];
        #pragma unroll
        for (int i = 0; i < 4; i++) { acc[i][0]=acc[i][1]=acc[i][2]=acc[i][3]=0.f; }
        gprod_tri(sb + ADJ_O + m0 * ST, sb + XH_O + m0 * ST,
                  sb + XL_O + n0 * ST, sb + WH_O + n0 * ST, lane, acc);
        #pragma unroll
        for (int nt = 0; nt < 4; nt++) {
            int c0 = 64 + n0 + nt * 8 + c0b;
            float u0 = s_u[c0], u1 = s_u[c0 + 1], w0 = s_wf2[c0], w1 = s_wf2[c0 + 1];
            p0 = fmaf(fmaxf(acc[nt][0] + u0, 0.f), w0, p0);
            p0 = fmaf(fmaxf(acc[nt][1] + u1, 0.f), w1, p0);
            p1 = fmaf(fmaxf(acc[nt][2] + u0, 0.f), w0, p1);
            p1 = fmaf(fmaxf(acc[nt][3] + u1, 0.f), w1, p1);
        }
    }
    p0 += __shfl_xor_sync(0xffffffffu, p0, 1); p0 += __shfl_xor_sync(0xffffffffu, p0, 2);
    p1 += __shfl_xor_sync(0xffffffffu, p1, 1); p1 += __shfl_xor_sync(0xffffffffu, p1, 2);
    if ((lane & 3) == 0) {
        s_part[ch2 * 64 + m0 + g] = p0;
        s_part[ch2 * 64 + m0 + g + 8] = p1;
    }
    __syncthreads();
    if (tid < 63) out[(size_t)b * 63 + tid] = s_part[tid] + s_part[64 + tid] + bf2[0];
}

extern "C" void kernel_launch(void* const* d_in, const int* in_sizes, int n_in,
                              void* d_out, int out_size)
{
    (void)in_sizes; (void)n_in; (void)out_size;
    cudaFuncSetAttribute(pgcn_main, cudaFuncAttributeMaxDynamicSharedMemorySize, SMEM_BYTES);
    pgcn_prep<<<64, 256>>>((const float*)d_in[7], (const float*)d_in[9],
                           (const float*)d_in[11], (const float*)d_in[13]);
    pgcn_main<<<16384, 256, SMEM_BYTES>>>(
        (const float*)d_in[0],  (const float*)d_in[1],  (const float*)d_in[2],
        (const float*)d_in[3],  (const float*)d_in[4],  (const float*)d_in[5],
        (const float*)d_in[6],  (const float*)d_in[8],  (const float*)d_in[10],
        (const float*)d_in[12], (const float*)d_in[13], (const float*)d_in[14],
        (const float*)d_in[15], (const float*)d_in[16], (float*)d_out);
}

// round 14
// speedup vs baseline: 1.6810x; 1.1566x over previous
#include <cuda_runtime.h>
#include <cuda_bf16.h>
#include <cstdint>

#define ST 144                  // row stride bytes (72 bf16): bank-rotating, 16B-aligned
#define ADJ_O 0                 // adjacency -> h3 hi
#define XH_O  9216              // X^T hi / T hi / h3 lo
#define XL_O  18432             // X^T lo / T lo / head: Wf1^T half1 hi
#define WH_O  27648             // W^T hi (emb: obs hi cols0-63 + embW hi cols64-127; head: Wf1^T half0 hi -> half1 lo)
#define WL_O  36864             // W^T lo (emb: obs lo + embW lo; head: Wf1^T half0 lo)
#define MLO_O  46080
#define MHI_O  46336
#define DINV_O 46592
#define BIAS_O 46848
#define U_O    47104
#define WF2_O  47616
#define MEAN_O 48128
#define H3S_O  48384
#define PART_O 48640            // float[2][64]
#define CS_O   49152            // emb biases (bd|bs) -> col-sums -> u partials
#define SMEM_BYTES 50176

static __device__ __align__(16) unsigned char g_WT[3][2][9216];   // W_L^T [n][k] hi/lo
static __device__ __align__(16) unsigned char g_Wf1T[2][18432];   // Wf1_dev^T [m][k] hi/lo
static __device__ __align__(16) unsigned char g_embWT[2][4096];   // combined emb W^T [c][k<32] hi/lo (64B rows)

__device__ __forceinline__ uint32_t smem_u32(const void* p) {
    uint32_t a;
    asm("{ .reg .u64 t; cvta.to.shared.u64 t, %1; cvt.u32.u64 %0, t; }" : "=r"(a) : "l"(p));
    return a;
}
__device__ __forceinline__ void ldsm4(uint32_t addr, uint32_t* r) {
    asm volatile("ldmatrix.sync.aligned.m8n8.x4.shared.b16 {%0,%1,%2,%3}, [%4];"
                 : "=r"(r[0]), "=r"(r[1]), "=r"(r[2]), "=r"(r[3]) : "r"(addr));
}
__device__ __forceinline__ void mma16816(float* d, const uint32_t* a, const uint32_t* b) {
    asm volatile("mma.sync.aligned.m16n8k16.row.col.f32.bf16.bf16.f32 "
        "{%0,%1,%2,%3}, {%4,%5,%6,%7}, {%8,%9}, {%0,%1,%2,%3};"
        : "+f"(d[0]), "+f"(d[1]), "+f"(d[2]), "+f"(d[3])
        : "r"(a[0]), "r"(a[1]), "r"(a[2]), "r"(a[3]), "r"(b[0]), "r"(b[1]));
}
__device__ __forceinline__ void sp1(float v, uint16_t& h, uint16_t& l) {
    __nv_bfloat16 hb = __float2bfloat16(v);
    __nv_bfloat16 lb = __float2bfloat16(v - __bfloat162float(hb));
    h = __bfloat16_as_ushort(hb); l = __bfloat16_as_ushort(lb);
}
// pack (a,b) -> hi bf16x2 + residual lo bf16x2
__device__ __forceinline__ uint32_t sp2(float a, float b, uint32_t& lo) {
    uint32_t hi;
    asm("cvt.rn.bf16x2.f32 %0, %1, %2;" : "=r"(hi) : "f"(b), "f"(a));
    float ha = __uint_as_float(hi << 16);
    float hb = __uint_as_float(hi & 0xffff0000u);
    asm("cvt.rn.bf16x2.f32 %0, %1, %2;" : "=r"(lo) : "f"(b - hb), "f"(a - ha));
    return hi;
}
// acc += A@B1^T + A@B2^T (A fragments loaded once); D(16x32), K=64
__device__ __forceinline__ void gprod_dualB(uint32_t aB, uint32_t b1B, uint32_t b2B,
                                            int lane, float (*acc)[4]) {
    const int arow = lane & 15, acol = (lane >> 4) << 3;
    const int brow = (lane & 7) + ((lane & 16) >> 1), bcol = lane & 8;
    #pragma unroll
    for (int kk = 0; kk < 64; kk += 16) {
        uint32_t a[4]; ldsm4(aB + arow * ST + (kk + acol) * 2, a);
        #pragma unroll
        for (int nt = 0; nt < 2; nt++) {
            uint32_t bf[4];
            ldsm4(b1B + (nt * 16 + brow) * ST + (kk + bcol) * 2, bf);
            mma16816(acc[nt * 2], a, bf);
            mma16816(acc[nt * 2 + 1], a, bf + 2);
            ldsm4(b2B + (nt * 16 + brow) * ST + (kk + bcol) * 2, bf);
            mma16816(acc[nt * 2], a, bf);
            mma16816(acc[nt * 2 + 1], a, bf + 2);
        }
    }
}
// acc += A1@B1^T + A1@B2^T + A2@B1^T — all fragments loaded once; K=64
__device__ __forceinline__ void gprod_tri(uint32_t a1B, uint32_t a2B,
                                          uint32_t b1B, uint32_t b2B,
                                          int lane, float (*acc)[4]) {
    const int arow = lane & 15, acol = (lane >> 4) << 3;
    const int brow = (lane & 7) + ((lane & 16) >> 1), bcol = lane & 8;
    #pragma unroll
    for (int kk = 0; kk < 64; kk += 16) {
        uint32_t a0[4], a1[4];
        ldsm4(a1B + arow * ST + (kk + acol) * 2, a0);
        ldsm4(a2B + arow * ST + (kk + acol) * 2, a1);
        #pragma unroll
        for (int nt = 0; nt < 2; nt++) {
            uint32_t bf[4];
            ldsm4(b1B + (nt * 16 + brow) * ST + (kk + bcol) * 2, bf);
            mma16816(acc[nt * 2], a0, bf);
            mma16816(acc[nt * 2 + 1], a0, bf + 2);
            mma16816(acc[nt * 2], a1, bf);
            mma16816(acc[nt * 2 + 1], a1, bf + 2);
            ldsm4(b2B + (nt * 16 + brow) * ST + (kk + bcol) * 2, bf);
            mma16816(acc[nt * 2], a0, bf);
            mma16816(acc[nt * 2 + 1], a0, bf + 2);
        }
    }
}
// same, K=32 (embedding)
__device__ __forceinline__ void gprod_tri32(uint32_t a1B, uint32_t a2B,
                                            uint32_t b1B, uint32_t b2B,
                                            int lane, float (*acc)[4]) {
    const int arow = lane & 15, acol = (lane >> 4) << 3;
    const int brow = (lane & 7) + ((lane & 16) >> 1), bcol = lane & 8;
    #pragma unroll
    for (int kk = 0; kk < 32; kk += 16) {
        uint32_t a0[4], a1[4];
        ldsm4(a1B + arow * ST + (kk + acol) * 2, a0);
        ldsm4(a2B + arow * ST + (kk + acol) * 2, a1);
        #pragma unroll
        for (int nt = 0; nt < 2; nt++) {
            uint32_t bf[4];
            ldsm4(b1B + (nt * 16 + brow) * ST + (kk + bcol) * 2, bf);
            mma16816(acc[nt * 2], a0, bf);
            mma16816(acc[nt * 2 + 1], a0, bf + 2);
            mma16816(acc[nt * 2], a1, bf);
            mma16816(acc[nt * 2 + 1], a1, bf + 2);
            ldsm4(b2B + (nt * 16 + brow) * ST + (kk + bcol) * 2, bf);
            mma16816(acc[nt * 2], a0, bf);
            mma16816(acc[nt * 2 + 1], a0, bf + 2);
        }
    }
}

__global__ void pgcn_prep(const float* __restrict__ W1, const float* __restrict__ W2,
                          const float* __restrict__ W3, const float* __restrict__ Wf1,
                          const float* __restrict__ W_dev, const float* __restrict__ W_srv) {
    const float* Ws[3] = {W1, W2, W3};
    int gt = blockIdx.x * blockDim.x + threadIdx.x, nth = gridDim.x * blockDim.x;
    for (int L = 0; L < 3; L++)
        for (int i = gt; i < 4096; i += nth) {
            int n = i >> 6, k = i & 63;
            uint16_t h, l; sp1(Ws[L][k * 64 + n], h, l);
            *(uint16_t*)(g_WT[L][0] + n * ST + k * 2) = h;
            *(uint16_t*)(g_WT[L][1] + n * ST + k * 2) = l;
        }
    for (int i = gt; i < 8192; i += nth) {
        int m = i >> 6, k = i & 63;
        uint16_t h, l; sp1(Wf1[k * 128 + m], h, l);
        *(uint16_t*)(g_Wf1T[0] + m * ST + k * 2) = h;
        *(uint16_t*)(g_Wf1T[1] + m * ST + k * 2) = l;
    }
    // combined emb weight: row c, k<14 = W_dev[k][c]; k=14..16 = W_srv[k-14][c]; else 0
    for (int i = gt; i < 2048; i += nth) {
        int c = i >> 5, k = i & 31;
        float v = (k < 14) ? W_dev[k * 64 + c] : (k < 17 ? W_srv[(k - 14) * 64 + c] : 0.0f);
        uint16_t h, l; sp1(v, h, l);
        *(uint16_t*)(g_embWT[0] + c * 64 + k * 2) = h;
        *(uint16_t*)(g_embWT[1] + c * 64 + k * 2) = l;
    }
}

__global__ __launch_bounds__(256, 4)
void pgcn_main(const float* __restrict__ dev_obs, const float* __restrict__ srv_obs,
               const float* __restrict__ adj,
               const float* __restrict__ b_dev, const float* __restrict__ b_srv,
               const float* __restrict__ b1, const float* __restrict__ b2,
               const float* __restrict__ b3,
               const float* __restrict__ Wf1, const float* __restrict__ bf1,
               const float* __restrict__ Wf2, const float* __restrict__ bf2,
               float* __restrict__ out)
{
    extern __shared__ __align__(16) unsigned char sm[];
    const uint32_t sb = smem_u32(sm);
    unsigned* s_mlo = (unsigned*)(sm + MLO_O);
    unsigned* s_mhi = (unsigned*)(sm + MHI_O);
    float* s_dinv = (float*)(sm + DINV_O);
    float* s_bias = (float*)(sm + BIAS_O);
    float* s_u    = (float*)(sm + U_O);
    float* s_wf2  = (float*)(sm + WF2_O);
    float* s_mean = (float*)(sm + MEAN_O);
    float* s_h3s  = (float*)(sm + H3S_O);
    float* s_part = (float*)(sm + PART_O);
    float* s_cs   = (float*)(sm + CS_O);    // emb biases -> col-sums -> u partials

    const int tid = threadIdx.x, lane = tid & 31, wid = tid >> 5;
    const int b = blockIdx.x;
    const int m0 = (wid & 3) * 16, ch2 = wid >> 2, n0 = ch2 * 32;
    const int g = lane >> 2, c0b = (lane & 3) * 2;

    // ---- stage obs bf16 tiles (rows of WH/WL, cols 0..31), embW (cols 64..127),
    //      emb biases into CS, masks + dinv ----
    if (tid < 64) {
        int n = tid;
        float v[32];
        #pragma unroll
        for (int k = 0; k < 32; k++) v[k] = 0.0f;
        if (n < 63) {
            const float* o = dev_obs + (size_t)b * 882 + n * 14;
            #pragma unroll
            for (int k = 0; k < 14; k++) v[k] = o[k];
        } else {
            #pragma unroll
            for (int k = 0; k < 3; k++) v[14 + k] = srv_obs[b * 3 + k];
        }
        #pragma unroll
        for (int j = 0; j < 16; j++) {
            uint32_t lo, hi = sp2(v[2 * j], v[2 * j + 1], lo);
            *(uint32_t*)(sm + WH_O + n * ST + j * 4) = hi;
            *(uint32_t*)(sm + WL_O + n * ST + j * 4) = lo;
        }
    } else if (tid < 128) {
        int i0 = tid - 64;
        for (int i = i0; i < 256; i += 64) {
            int row = i >> 2, q = i & 3;
            *(uint4*)(sm + WH_O + row * ST + 64 + q * 16) =
                *(const uint4*)(g_embWT[0] + row * 64 + q * 16);
            *(uint4*)(sm + WL_O + row * ST + 64 + q * 16) =
                *(const uint4*)(g_embWT[1] + row * 64 + q * 16);
        }
    } else if (tid < 192) {
        int i = tid - 128;
        s_cs[i] = b_dev[i];
        s_cs[64 + i] = b_srv[i];
    }
    {
        const float* ar = adj + (size_t)b * 4096;
        for (int r = wid; r < 64; r += 8) {
            unsigned a0 = __ballot_sync(0xffffffffu, ar[r * 64 + lane] != 0.0f);
            unsigned a1 = __ballot_sync(0xffffffffu, ar[r * 64 + 32 + lane] != 0.0f);
            if (lane == 0) {
                s_mlo[r] = a0; s_mhi[r] = a1;
                s_dinv[r] = rsqrtf(fmaxf((float)(__popc(a0) + __popc(a1)), 1.0f));
            }
        }
    }
    __syncthreads();

    // ---- adjacency bf16 tile ----
    for (int i = tid; i < 512; i += 256) {
        int r = i >> 3, chk = i & 7;
        unsigned byte8 = ((chk < 4 ? s_mlo[r] : s_mhi[r]) >> ((chk & 3) * 8)) & 0xFF;
        uint4 v; uint32_t* vp = (uint32_t*)&v;
        #pragma unroll
        for (int j = 0; j < 4; j++) {
            unsigned b2 = (byte8 >> (2 * j)) & 3;
            vp[j] = ((b2 & 1) ? 0x3F80u : 0u) | ((b2 & 2) ? 0x3F800000u : 0u);
        }
        *(uint4*)(sm + ADJ_O + r * ST + chk * 16) = v;
    }
    // ---- embedding GEMM: D[c][n] = embW @ obs^T (tri-fused split, K=32) ----
    {
        float acc[4][4];
        #pragma unroll
        for (int i = 0; i < 4; i++) { acc[i][0]=acc[i][1]=acc[i][2]=acc[i][3]=0.f; }
        gprod_tri32(sb + WH_O + 64 + m0 * ST, sb + WL_O + 64 + m0 * ST,
                    sb + WH_O + n0 * ST, sb + WL_O + n0 * ST, lane, acc);
        // epilogue: X^T[c][n] = relu(D + bias(c,n)) * dinv[n]  (bias: b_srv at n==63)
        const int cA0 = m0 + g, cA1 = cA0 + 8;
        float bd0 = s_cs[cA0], bd1 = s_cs[cA1];
        float bs0 = s_cs[64 + cA0], bs1 = s_cs[64 + cA1];
        #pragma unroll
        for (int nt = 0; nt < 4; nt++) {
            int r0 = n0 + nt * 8 + c0b;
            float da = s_dinv[r0], db = s_dinv[r0 + 1];
            float bb0a = (r0 == 63) ? bs0 : bd0, bb0b = (r0 + 1 == 63) ? bs0 : bd0;
            float bb1a = (r0 == 63) ? bs1 : bd1, bb1b = (r0 + 1 == 63) ? bs1 : bd1;
            uint32_t lo, hi;
            hi = sp2(fmaxf(acc[nt][0] + bb0a, 0.f) * da,
                     fmaxf(acc[nt][1] + bb0b, 0.f) * db, lo);
            *(uint32_t*)(sm + XH_O + cA0 * ST + r0 * 2) = hi;
            *(uint32_t*)(sm + XL_O + cA0 * ST + r0 * 2) = lo;
            hi = sp2(fmaxf(acc[nt][2] + bb1a, 0.f) * da,
                     fmaxf(acc[nt][3] + bb1b, 0.f) * db, lo);
            *(uint32_t*)(sm + XH_O + cA1 * ST + r0 * 2) = hi;
            *(uint32_t*)(sm + XL_O + cA1 * ST + r0 * 2) = lo;
        }
    }
    __syncthreads();

    // ---- 3 GCN layers ----
    #pragma unroll 1
    for (int L = 0; L < 3; L++) {
        {   // stage W^T hi/lo + bias
            const uint4* wh = (const uint4*)g_WT[L][0];
            const uint4* wl = (const uint4*)g_WT[L][1];
            for (int i = tid; i < 576; i += 256) {
                ((uint4*)(sm + WH_O))[i] = wh[i];
                ((uint4*)(sm + WL_O))[i] = wl[i];
            }
            const float* bl = (L == 0) ? b1 : (L == 1) ? b2 : b3;
            if (tid < 64) s_bias[tid] = bl[tid];
        }
        // aggregation: D[r][c] = Adj @ (XH + XL)^T
        float acc[4][4];
        #pragma unroll
        for (int i = 0; i < 4; i++) { acc[i][0]=acc[i][1]=acc[i][2]=acc[i][3]=0.f; }
        gprod_dualB(sb + ADJ_O + m0 * ST, sb + XH_O + n0 * ST, sb + XL_O + n0 * ST, lane, acc);
        __syncthreads();   // all X reads done; W staged

        // epi1: T[r][c] = dinv[r]*D -> overwrite XH/XL (T tiles)
        {
            const int r0 = m0 + g, r1 = r0 + 8;
            float d0 = s_dinv[r0], d1 = s_dinv[r1];
            #pragma unroll
            for (int nt = 0; nt < 4; nt++) {
                int c0 = n0 + nt * 8 + c0b;
                uint32_t lo, hi;
                hi = sp2(acc[nt][0] * d0, acc[nt][1] * d0, lo);
                *(uint32_t*)(sm + XH_O + r0 * ST + c0 * 2) = hi;
                *(uint32_t*)(sm + XL_O + r0 * ST + c0 * 2) = lo;
                hi = sp2(acc[nt][2] * d1, acc[nt][3] * d1, lo);
                *(uint32_t*)(sm + XH_O + r1 * ST + c0 * 2) = hi;
                *(uint32_t*)(sm + XL_O + r1 * ST + c0 * 2) = lo;
            }
        }
        __syncthreads();   // T visible

        #pragma unroll
        for (int i = 0; i < 4; i++) { acc[i][0]=acc[i][1]=acc[i][2]=acc[i][3]=0.f; }
        if (L < 2) {
            // gemm (transposed out): D[c][r] = Whi·(Thi+Tlo) + Wlo·Thi (tri-fused)
            gprod_tri(sb + WH_O + m0 * ST, sb + WL_O + m0 * ST,
                      sb + XH_O + n0 * ST, sb + XL_O + n0 * ST, lane, acc);
            __syncthreads();   // all T reads done
            // epi2: X^T[c][r] = relu(D + b[c]) * dinv[r]
            const int cA0 = m0 + g, cA1 = cA0 + 8;
            float bA0 = s_bias[cA0], bA1 = s_bias[cA1];
            #pragma unroll
            for (int nt = 0; nt < 4; nt++) {
                int r0 = n0 + nt * 8 + c0b;
                float da = s_dinv[r0], db = s_dinv[r0 + 1];
                uint32_t lo, hi;
                hi = sp2(fmaxf(acc[nt][0] + bA0, 0.f) * da,
                         fmaxf(acc[nt][1] + bA0, 0.f) * db, lo);
                *(uint32_t*)(sm + XH_O + cA0 * ST + r0 * 2) = hi;
                *(uint32_t*)(sm + XL_O + cA0 * ST + r0 * 2) = lo;
                hi = sp2(fmaxf(acc[nt][2] + bA1, 0.f) * da,
                         fmaxf(acc[nt][3] + bA1, 0.f) * db, lo);
                *(uint32_t*)(sm + XH_O + cA1 * ST + r0 * 2) = hi;
                *(uint32_t*)(sm + XL_O + cA1 * ST + r0 * 2) = lo;
            }
        } else {
            // gemm3: D[r][c] = (Thi+Tlo)·Whi + Thi·Wlo  (node-major h3, tri-fused)
            gprod_tri(sb + XH_O + m0 * ST, sb + XL_O + m0 * ST,
                      sb + WH_O + n0 * ST, sb + WL_O + n0 * ST, lane, acc);
            __syncthreads();
            // epi3: h3 = relu(D + b[c]); hi->ADJ, lo->XH; col-sums + server row
            const int r0 = m0 + g, r1 = r0 + 8;
            const bool srvlane = (m0 == 48) && (g == 7);   // r1 == 63
            float csA[4], csB[4];
            #pragma unroll
            for (int nt = 0; nt < 4; nt++) {
                int c0 = n0 + nt * 8 + c0b;
                float b0v = s_bias[c0], b1v = s_bias[c0 + 1];
                float v0 = fmaxf(acc[nt][0] + b0v, 0.f);
                float v1 = fmaxf(acc[nt][1] + b1v, 0.f);
                float v2 = fmaxf(acc[nt][2] + b0v, 0.f);
                float v3 = fmaxf(acc[nt][3] + b1v, 0.f);
                uint32_t lo, hi;
                hi = sp2(v0, v1, lo);
                *(uint32_t*)(sm + ADJ_O + r0 * ST + c0 * 2) = hi;
                *(uint32_t*)(sm + XH_O + r0 * ST + c0 * 2) = lo;
                hi = sp2(v2, v3, lo);
                *(uint32_t*)(sm + ADJ_O + r1 * ST + c0 * 2) = hi;
                *(uint32_t*)(sm + XH_O + r1 * ST + c0 * 2) = lo;
                csA[nt] = v0 + (srvlane ? 0.f : v2);
                csB[nt] = v1 + (srvlane ? 0.f : v3);
                if (srvlane) { s_h3s[c0] = v2; s_h3s[c0 + 1] = v3; }
            }
            #pragma unroll
            for (int off = 4; off < 32; off <<= 1) {
                #pragma unroll
                for (int nt = 0; nt < 4; nt++) {
                    csA[nt] += __shfl_xor_sync(0xffffffffu, csA[nt], off);
                    csB[nt] += __shfl_xor_sync(0xffffffffu, csB[nt], off);
                }
            }
            if (g == 0) {
                float* cs = s_cs + (m0 >> 4) * 64;
                #pragma unroll
                for (int nt = 0; nt < 4; nt++) {
                    int c0 = n0 + nt * 8 + c0b;
                    cs[c0] = csA[nt]; cs[c0 + 1] = csB[nt];
                }
            }
        }
        __syncthreads();
    }

    // ---- P1: mean from col-sums (tid<64) || stage Wf1^T half0 hi/lo + half1 hi + wf2 ----
    if (tid < 64) {
        s_mean[tid] = (s_cs[tid] + s_cs[64 + tid] + s_cs[128 + tid] + s_cs[192 + tid])
                      * (1.0f / 63.0f);
    } else {
        const uint4* hh = (const uint4*)g_Wf1T[0];
        const uint4* hl = (const uint4*)g_Wf1T[1];
        for (int i = tid - 64; i < 576; i += 192) {
            ((uint4*)(sm + WH_O))[i] = hh[i];
            ((uint4*)(sm + WL_O))[i] = hl[i];
            ((uint4*)(sm + XL_O))[i] = hh[576 + i];   // half1 hi pre-staged
        }
        if (tid - 64 < 128) s_wf2[tid - 64] = Wf2[tid - 64];
    }
    __syncthreads();
    {   // u partials: 256 threads, half the k-range each (overlays s_cs)
        int m = tid & 127, half = tid >> 7, k0 = half * 32;
        float acc = 0.0f;
        #pragma unroll 4
        for (int k = k0; k < k0 + 32; k++) acc = fmaf(s_mean[k], Wf1[(64 + k) * 128 + m], acc);
        #pragma unroll 4
        for (int k = k0; k < k0 + 32; k++) acc = fmaf(s_h3s[k], Wf1[(128 + k) * 128 + m], acc);
        s_cs[tid] = acc;
    }
    __syncthreads();
    if (tid < 128) s_u[tid] = bf1[tid] + s_cs[tid] + s_cs[128 + tid];
    __syncthreads();

    // ---- head GEMM half 0 (B = WH/WL, tri-fused) ----
    float p0 = 0.f, p1 = 0.f;
    {
        float acc[4][4];
        #pragma unroll
        for (int i = 0; i < 4; i++) { acc[i][0]=acc[i][1]=acc[i][2]=acc[i][3]=0.f; }
        gprod_tri(sb + ADJ_O + m0 * ST, sb + XH_O + m0 * ST,
                  sb + WH_O + n0 * ST, sb + WL_O + n0 * ST, lane, acc);
        #pragma unroll
        for (int nt = 0; nt < 4; nt++) {
            int c0 = n0 + nt * 8 + c0b;
            float u0 = s_u[c0], u1 = s_u[c0 + 1], w0 = s_wf2[c0], w1 = s_wf2[c0 + 1];
            p0 = fmaf(fmaxf(acc[nt][0] + u0, 0.f), w0, p0);
            p0 = fmaf(fmaxf(acc[nt][1] + u1, 0.f), w1, p0);
            p1 = fmaf(fmaxf(acc[nt][2] + u0, 0.f), w0, p1);
            p1 = fmaf(fmaxf(acc[nt][3] + u1, 0.f), w1, p1);
        }
    }
    __syncthreads();   // WH reads done
    {   // stage half1 lo into WH (9KB)
        const uint4* hl = (const uint4*)(g_Wf1T[1] + 9216);
        for (int i = tid; i < 576; i += 256) ((uint4*)(sm + WH_O))[i] = hl[i];
    }
    __syncthreads();
    // ---- head GEMM half 1 (B hi = XL pre-staged, lo = WH, tri-fused) ----
    {
        float acc[4][4];
        #pragma unroll
        for (int i = 0; i < 4; i++) { acc[i][0]=acc[i][1]=acc[i][2]=acc[i][3]=0.f; }
        gprod_tri(sb + ADJ_O + m0 * ST, sb + XH_O + m0 * ST,
                  sb + XL_O + n0 * ST, sb + WH_O + n0 * ST, lane, acc);
        #pragma unroll
        for (int nt = 0; nt < 4; nt++) {
            int c0 = 64 + n0 + nt * 8 + c0b;
            float u0 = s_u[c0], u1 = s_u[c0 + 1], w0 = s_wf2[c0], w1 = s_wf2[c0 + 1];
            p0 = fmaf(fmaxf(acc[nt][0] + u0, 0.f), w0, p0);
            p0 = fmaf(fmaxf(acc[nt][1] + u1, 0.f), w1, p0);
            p1 = fmaf(fmaxf(acc[nt][2] + u0, 0.f), w0, p1);
            p1 = fmaf(fmaxf(acc[nt][3] + u1, 0.f), w1, p1);
        }
    }
    p0 += __shfl_xor_sync(0xffffffffu, p0, 1); p0 += __shfl_xor_sync(0xffffffffu, p0, 2);
    p1 += __shfl_xor_sync(0xffffffffu, p1, 1); p1 += __shfl_xor_sync(0xffffffffu, p1, 2);
    if ((lane & 3) == 0) {
        s_part[ch2 * 64 + m0 + g] = p0;
        s_part[ch2 * 64 + m0 + g + 8] = p1;
    }
    __syncthreads();
    if (tid < 63) out[(size_t)b * 63 + tid] = s_part[tid] + s_part[64 + tid] + bf2[0];
}

extern "C" void kernel_launch(void* const* d_in, const int* in_sizes, int n_in,
                              void* d_out, int out_size)
{
    (void)in_sizes; (void)n_in; (void)out_size;
    cudaFuncSetAttribute(pgcn_main, cudaFuncAttributeMaxDynamicSharedMemorySize, SMEM_BYTES);
    pgcn_prep<<<64, 256>>>((const float*)d_in[7], (const float*)d_in[9],
                           (const float*)d_in[11], (const float*)d_in[13],
                           (const float*)d_in[3], (const float*)d_in[5]);
    pgcn_main<<<16384, 256, SMEM_BYTES>>>(
        (const float*)d_in[0],  (const float*)d_in[1],  (const float*)d_in[2],
        (const float*)d_in[4],  (const float*)d_in[6],  (const float*)d_in[8],
        (const float*)d_in[10], (const float*)d_in[12], (const float*)d_in[13],
        (const float*)d_in[14], (const float*)d_in[15], (const float*)d_in[16],
        (float*)d_out);
}